// round 3
// baseline (speedup 1.0000x reference)
#include <cuda_runtime.h>
#include <cstdint>

#define NPTS 8192
#define NS   2048
#define NK   32
#define NB   4
#define MPB  65536              /* NK*NS per batch */
#define FSZ  (NB*64*MPB)        /* 16.7M floats per feature buffer */

__device__ float g_y0[FSZ];
__device__ float g_t1[FSZ];
__device__ float g_t2[FSZ];
__device__ float g_x1[FSZ];
__device__ float g_nxyz[NB*NS*3];
__device__ int   g_idx[NB*NK*NS];
__device__ float g_ps[256];
__device__ float g_pq[256];
__device__ float g_aff[5*128];

static __device__ __forceinline__ unsigned long long pk2(float lo, float hi){
    unsigned long long r; asm("mov.b64 %0,{%1,%2};" : "=l"(r) : "f"(lo), "f"(hi)); return r;
}
static __device__ __forceinline__ void upk2(unsigned long long v, float& lo, float& hi){
    asm("mov.b64 {%0,%1},%2;" : "=f"(lo), "=f"(hi) : "l"(v));
}
static __device__ __forceinline__ unsigned long long f2fma(unsigned long long a, unsigned long long b, unsigned long long c){
    unsigned long long r; asm("fma.rn.f32x2 %0,%1,%2,%3;" : "=l"(r) : "l"(a), "l"(b), "l"(c)); return r;
}
static __device__ __forceinline__ unsigned long long f2mul(unsigned long long a, unsigned long long b){
    unsigned long long r; asm("mul.rn.f32x2 %0,%1,%2;" : "=l"(r) : "l"(a), "l"(b)); return r;
}
static __device__ __forceinline__ unsigned long long f2add(unsigned long long a, unsigned long long b){
    unsigned long long r; asm("add.rn.f32x2 %0,%1,%2;" : "=l"(r) : "l"(a), "l"(b)); return r;
}
static __device__ __forceinline__ unsigned long long f2sub(unsigned long long a, unsigned long long b){
    unsigned long long r; asm("sub.rn.f32x2 %0,%1,%2;" : "=l"(r) : "l"(a), "l"(b)); return r;
}

// ---------------- FPS: one block per batch, 1 barrier/iteration ----------------
// All 8192 points mirrored in dynamic smem (float4, 128KB) so every thread can
// fetch the winner's coords by index after the reduction. Cross-warp argmax via
// 64-bit atomicMax of (key<<32)|(~idx) into a 3-slot rotating accumulator.
extern __shared__ float4 spts[];

__global__ __launch_bounds__(1024, 1) void fps_kernel(const float* __restrict__ xyz,
                                                      float* __restrict__ outxyz,
                                                      float* __restrict__ nxyz)
{
    int b = blockIdx.x, tid = threadIdx.x;
    int lane = tid & 31;
    const float* X = xyz + (size_t)b * 3 * NPTS;

    __shared__ unsigned long long slot[3];

    unsigned long long x2[4], y2[4], z2[4];
    float dist[8];
#pragma unroll
    for (int p = 0; p < 4; ++p) {
        int na = tid + (2*p)   * 1024;
        int nb = tid + (2*p+1) * 1024;
        float xa = X[na],        xbv = X[nb];
        float ya = X[NPTS+na],   yb  = X[NPTS+nb];
        float za = X[2*NPTS+na], zb  = X[2*NPTS+nb];
        x2[p] = pk2(xa, xbv); y2[p] = pk2(ya, yb); z2[p] = pk2(za, zb);
        spts[na] = make_float4(xa, ya, za, 0.f);
        spts[nb] = make_float4(xbv, yb, zb, 0.f);
        dist[2*p] = 1e10f; dist[2*p+1] = 1e10f;
    }
    if (tid < 3) slot[tid] = 0ull;
    __syncthreads();

    float4 c0 = spts[0];
    float cx = c0.x, cy = c0.y, cz = c0.z;

    for (int it = 0; it < NS; ++it) {
        if (tid == 0) {
            outxyz[(b*3 + 0)*NS + it] = cx;
            outxyz[(b*3 + 1)*NS + it] = cy;
            outxyz[(b*3 + 2)*NS + it] = cz;
            nxyz[((size_t)b*NS + it)*3 + 0] = cx;
            nxyz[((size_t)b*NS + it)*3 + 1] = cy;
            nxyz[((size_t)b*NS + it)*3 + 2] = cz;
        }
        unsigned long long cx2 = pk2(cx, cx);
        unsigned long long cy2 = pk2(cy, cy);
        unsigned long long cz2 = pk2(cz, cz);

        float bk = -1.f; int bn = 0;
#pragma unroll
        for (int p = 0; p < 4; ++p) {
            unsigned long long dx = f2sub(x2[p], cx2);
            unsigned long long dy = f2sub(y2[p], cy2);
            unsigned long long dz = f2sub(z2[p], cz2);
            // (dx*dx + dy*dy) + dz*dz -- lane-wise identical to scalar mul/add rounding
            unsigned long long s = f2add(f2add(f2mul(dx, dx), f2mul(dy, dy)), f2mul(dz, dz));
            float s0, s1; upk2(s, s0, s1);
            float d0 = fminf(dist[2*p],   s0);
            float d1 = fminf(dist[2*p+1], s1);
            dist[2*p] = d0; dist[2*p+1] = d1;
            if (d0 > bk) { bk = d0; bn = tid + (2*p)   * 1024; }
            if (d1 > bk) { bk = d1; bn = tid + (2*p+1) * 1024; }
        }
        // warp argmax: max key, then min index among key==max (first-occurrence)
        unsigned key  = __float_as_uint(bk);                // dist >= 0 -> monotonic
        unsigned kmax = __reduce_max_sync(0xffffffffu, key);
        unsigned cand = (key == kmax) ? (unsigned)bn : 0xffffffffu;
        unsigned imin = __reduce_min_sync(0xffffffffu, cand);
        if (lane == 0)
            atomicMax(&slot[it % 3],
                      ((unsigned long long)kmax << 32) |
                      (unsigned long long)(0xffffffffu - imin));
        if (tid == 0) slot[(it + 1) % 3] = 0ull;   // safe: last touched 2 barriers ago
        __syncthreads();
        unsigned long long win = slot[it % 3];
        int widx = (int)(0xffffffffu - (unsigned)(win & 0xffffffffu));
        float4 cc = spts[widx];
        cx = cc.x; cy = cc.y; cz = cc.z;
    }
}

// ---------------- ball query: one warp per center ----------------
__global__ __launch_bounds__(256) void ball_kernel(const float* __restrict__ xyz,
                                                   const float* __restrict__ nxyz,
                                                   int* __restrict__ gidx)
{
    __shared__ int sbuf[8][32];
    int w = threadIdx.x >> 5, lane = threadIdx.x & 31;
    int gid = blockIdx.x * 8 + w;              // B*S = 8192 centers
    int b = gid >> 11, s = gid & 2047;
    const float* X = xyz + (size_t)b * 3 * NPTS;

    float cx = nxyz[gid*3], cy = nxyz[gid*3 + 1], cz = nxyz[gid*3 + 2];
    float cc = __fadd_rn(__fadd_rn(__fmul_rn(cx,cx), __fmul_rn(cy,cy)), __fmul_rn(cz,cz));
    const float R2 = (float)(0.1 * 0.1);

    int cnt = 0;
    for (int base = 0; base < NPTS; base += 32) {
        int n = base + lane;
        float px = X[n], py = X[NPTS + n], pz = X[2*NPTS + n];
        float pp  = __fadd_rn(__fadd_rn(__fmul_rn(px,px), __fmul_rn(py,py)), __fmul_rn(pz,pz));
        float dot = __fadd_rn(__fadd_rn(__fmul_rn(cx,px), __fmul_rn(cy,py)), __fmul_rn(cz,pz));
        float sqr = __fadd_rn(__fadd_rn(cc, pp), -__fmul_rn(2.f, dot));
        bool hit = (sqr <= R2);
        unsigned m = __ballot_sync(0xffffffffu, hit);
        if (m) {
            int rank = cnt + __popc(m & ((1u << lane) - 1u));
            if (hit && rank < 32) sbuf[w][rank] = n;
            cnt += __popc(m);
            if (cnt >= 32) break;
        }
    }
    __syncwarp();
    int first = sbuf[w][0];                    // center always in-radius -> cnt >= 1
    int my = (lane < cnt) ? sbuf[w][lane] : first;
    gidx[((size_t)(b*32 + lane))*2048 + s] = my;
}

// ---------------- gather + center-subtract + concat ----------------
__global__ __launch_bounds__(256) void gather_kernel(const float* __restrict__ xyz,
                                                     const float* __restrict__ pts,
                                                     const int* __restrict__ gidx,
                                                     const float* __restrict__ nxyz,
                                                     float* __restrict__ xin)
{
    int g = blockIdx.x * 256 + threadIdx.x;    // 262144 (b,k,s)
    int s = g & 2047, k = (g >> 11) & 31, b = g >> 16;
    int id = gidx[((size_t)(b*32 + k))*2048 + s];
    const float* X = xyz + (size_t)b * 3 * NPTS;
    const float* P = pts + (size_t)b * 29 * NPTS;
    size_t ob = (size_t)b * 32 * MPB + (size_t)k * 2048 + s;
#pragma unroll
    for (int c = 0; c < 3; ++c)
        xin[ob + (size_t)c * MPB] = X[c*NPTS + id] - nxyz[((size_t)(b*2048 + s))*3 + c];
#pragma unroll
    for (int c = 0; c < 29; ++c)
        xin[ob + (size_t)(3 + c) * MPB] = P[c*NPTS + id];
}

// ---------------- conv: out[b][o][m] = sum_c W[o][c] * act(in[b][c][m]) ----------------
template<int CIN, bool ACT>
__global__ __launch_bounds__(128) void conv_kernel(const float* __restrict__ in,
                                                   const float* __restrict__ W,
                                                   const float* __restrict__ aff,
                                                   float* __restrict__ out)
{
    __shared__ float sW[CIN][64];
    __shared__ float sA[64], sD[64];
    int tid = threadIdx.x;
    for (int i = tid; i < CIN * 64; i += 128)
        sW[i >> 6][i & 63] = W[(i & 63) * CIN + (i >> 6)];
    if (ACT && tid < CIN) { sA[tid] = aff[tid]; sD[tid] = aff[64 + tid]; }
    __syncthreads();

    int b = blockIdx.x >> 9;
    int m = ((blockIdx.x & 511) << 7) + ((tid & 31) << 2);
    int og = (tid >> 5) << 4;                  // 16 outputs per thread
    const float* ip = in + (size_t)b * CIN * MPB + m;

    unsigned long long acc[8][4];
#pragma unroll
    for (int p = 0; p < 8; ++p)
#pragma unroll
        for (int j = 0; j < 4; ++j) acc[p][j] = 0ull;

    float4 xv = *(const float4*)(ip);          // prefetch c=0
#pragma unroll 8
    for (int c = 0; c < CIN; ++c) {
        float4 xn;
        if (c + 1 < CIN) xn = *(const float4*)(ip + (size_t)(c + 1) * MPB);
        float4 x = xv;
        if (ACT) {
            float a = sA[c], d = sD[c];
            x.x = fmaxf(fmaf(a, x.x, d), 0.f);
            x.y = fmaxf(fmaf(a, x.y, d), 0.f);
            x.z = fmaxf(fmaf(a, x.z, d), 0.f);
            x.w = fmaxf(fmaf(a, x.w, d), 0.f);
        }
        unsigned long long xp[4] = { pk2(x.x, x.x), pk2(x.y, x.y),
                                     pk2(x.z, x.z), pk2(x.w, x.w) };
        const double2* wp = (const double2*)&sW[c][og];
        double2 w0 = wp[0], w1 = wp[1], w2 = wp[2], w3 = wp[3];
        unsigned long long wq[8] = {
            __double_as_longlong(w0.x), __double_as_longlong(w0.y),
            __double_as_longlong(w1.x), __double_as_longlong(w1.y),
            __double_as_longlong(w2.x), __double_as_longlong(w2.y),
            __double_as_longlong(w3.x), __double_as_longlong(w3.y) };
#pragma unroll
        for (int p = 0; p < 8; ++p)
#pragma unroll
            for (int j = 0; j < 4; ++j)
                acc[p][j] = f2fma(wq[p], xp[j], acc[p][j]);
        xv = xn;
    }

    float* op = out + (size_t)b * 64 * MPB + m;
#pragma unroll
    for (int p = 0; p < 8; ++p)
#pragma unroll
        for (int j = 0; j < 4; ++j) {
            float lo, hi; upk2(acc[p][j], lo, hi);
            op[(size_t)(og + 2*p)     * MPB + j] = lo;
            op[(size_t)(og + 2*p + 1) * MPB + j] = hi;
        }
}

// ---------------- per-channel stats (two-stage, deterministic) ----------------
__global__ __launch_bounds__(256) void stats1_kernel(const float* __restrict__ in,
                                                     float* __restrict__ ps,
                                                     float* __restrict__ pq)
{
    int o = blockIdx.x >> 2, b = blockIdx.x & 3;
    const float4* p = (const float4*)(in + (size_t)(b*64 + o) * MPB);
    float s = 0.f, q = 0.f;
    for (int i = threadIdx.x; i < MPB/4; i += 256) {
        float4 v = p[i];
        s += v.x + v.y + v.z + v.w;
        q += v.x*v.x + v.y*v.y + v.z*v.z + v.w*v.w;
    }
    __shared__ float rs[256], rq[256];
    rs[threadIdx.x] = s; rq[threadIdx.x] = q;
    for (int off = 128; off; off >>= 1) {
        __syncthreads();
        if (threadIdx.x < off) { rs[threadIdx.x] += rs[threadIdx.x + off];
                                 rq[threadIdx.x] += rq[threadIdx.x + off]; }
    }
    if (threadIdx.x == 0) { ps[blockIdx.x] = rs[0]; pq[blockIdx.x] = rq[0]; }
}

__global__ void statsfin_kernel(const float* __restrict__ ps, const float* __restrict__ pq,
                                const float* __restrict__ gam, const float* __restrict__ bet,
                                float* __restrict__ aff)
{
    int o = threadIdx.x;                       // 64 threads
    float s = ps[o*4] + ps[o*4+1] + ps[o*4+2] + ps[o*4+3];
    float q = pq[o*4] + pq[o*4+1] + pq[o*4+2] + pq[o*4+3];
    const float invn = 1.f / (float)(NB * MPB);
    float mean = s * invn;
    float var  = q * invn - mean * mean;
    float a = gam[o] * rsqrtf(var + 1e-5f);
    aff[o] = a;
    aff[64 + o] = bet[o] - a * mean;
}

// ---------------- residual: x1 = relu(aff2(t2) + relu(aff0(y0))) ----------------
__global__ __launch_bounds__(256) void resid_kernel(const float* __restrict__ y0,
                                                    const float* __restrict__ t2,
                                                    const float* __restrict__ aff0,
                                                    const float* __restrict__ aff2,
                                                    float* __restrict__ x1)
{
    size_t i = (size_t)blockIdx.x * 256 + threadIdx.x;   // float4 index, 4.19M
    int c = (int)((i >> 14) & 63);
    float a0 = aff0[c], d0 = aff0[64+c], a2 = aff2[c], d2 = aff2[64+c];
    float4 y = ((const float4*)y0)[i];
    float4 t = ((const float4*)t2)[i];
    float4 r;
    r.x = fmaxf(fmaf(a2, t.x, d2) + fmaxf(fmaf(a0, y.x, d0), 0.f), 0.f);
    r.y = fmaxf(fmaf(a2, t.y, d2) + fmaxf(fmaf(a0, y.y, d0), 0.f), 0.f);
    r.z = fmaxf(fmaf(a2, t.z, d2) + fmaxf(fmaf(a0, y.z, d0), 0.f), 0.f);
    r.w = fmaxf(fmaf(a2, t.w, d2) + fmaxf(fmaf(a0, y.w, d0), 0.f), 0.f);
    ((float4*)x1)[i] = r;
}

// ---------------- final: feat = max_k relu(aff4(t4) + x1) ----------------
__global__ __launch_bounds__(256) void finalmax_kernel(const float* __restrict__ t4,
                                                       const float* __restrict__ x1,
                                                       const float* __restrict__ aff,
                                                       float* __restrict__ outf)
{
    int g = blockIdx.x * 256 + threadIdx.x;    // 524288 = (b,o,s)
    int s = g & 2047, o = (g >> 11) & 63, b = g >> 17;
    float a = aff[o], d = aff[64 + o];
    size_t base = (size_t)(b*64 + o) * MPB + s;
    const float* tp = t4 + base;
    const float* xp = x1 + base;
    float m = -1e30f;
#pragma unroll 8
    for (int k = 0; k < 32; ++k)
        m = fmaxf(m, fmaf(a, tp[(size_t)k*2048], d) + xp[(size_t)k*2048]);
    outf[g] = fmaxf(m, 0.f);                   // max_k relu == relu(max_k)
}

extern "C" void kernel_launch(void* const* d_in, const int* in_sizes, int n_in,
                              void* d_out, int out_size)
{
    (void)in_sizes; (void)n_in; (void)out_size;
    const float* xyz = (const float*)d_in[0];
    const float* pts = (const float*)d_in[1];
    const float* pw  = (const float*)d_in[2];
    const float* pg  = (const float*)d_in[3];
    const float* pb  = (const float*)d_in[4];
    const float* w1  = (const float*)d_in[5];
    const float* g1  = (const float*)d_in[6];
    const float* b1  = (const float*)d_in[7];
    const float* w2  = (const float*)d_in[8];
    const float* g2  = (const float*)d_in[9];
    const float* b2  = (const float*)d_in[10];

    float *y0, *t1, *t2, *x1, *nx, *ps, *pq, *aff; int* gi;
    cudaGetSymbolAddress((void**)&y0,  g_y0);
    cudaGetSymbolAddress((void**)&t1,  g_t1);
    cudaGetSymbolAddress((void**)&t2,  g_t2);
    cudaGetSymbolAddress((void**)&x1,  g_x1);
    cudaGetSymbolAddress((void**)&nx,  g_nxyz);
    cudaGetSymbolAddress((void**)&gi,  g_idx);
    cudaGetSymbolAddress((void**)&ps,  g_ps);
    cudaGetSymbolAddress((void**)&pq,  g_pq);
    cudaGetSymbolAddress((void**)&aff, g_aff);
    float* out = (float*)d_out;

    cudaFuncSetAttribute(fps_kernel, cudaFuncAttributeMaxDynamicSharedMemorySize,
                         NPTS * (int)sizeof(float4));

    fps_kernel<<<NB, 1024, NPTS * sizeof(float4)>>>(xyz, out, nx);
    ball_kernel<<<1024, 256>>>(xyz, nx, gi);
    gather_kernel<<<1024, 256>>>(xyz, pts, gi, nx, t2);

    conv_kernel<32, false><<<2048, 128>>>(t2, pw, nullptr, y0);
    stats1_kernel<<<256, 256>>>(y0, ps, pq);
    statsfin_kernel<<<1, 64>>>(ps, pq, pg, pb, aff);

    conv_kernel<64, true><<<2048, 128>>>(y0, w1, aff, t1);
    stats1_kernel<<<256, 256>>>(t1, ps, pq);
    statsfin_kernel<<<1, 64>>>(ps, pq, g1, b1, aff + 128);

    conv_kernel<64, true><<<2048, 128>>>(t1, w2, aff + 128, t2);
    stats1_kernel<<<256, 256>>>(t2, ps, pq);
    statsfin_kernel<<<1, 64>>>(ps, pq, g2, b2, aff + 256);

    resid_kernel<<<16384, 256>>>(y0, t2, aff, aff + 256, x1);

    conv_kernel<64, false><<<2048, 128>>>(x1, w1 + 4096, nullptr, t1);
    stats1_kernel<<<256, 256>>>(t1, ps, pq);
    statsfin_kernel<<<1, 64>>>(ps, pq, g1 + 64, b1 + 64, aff + 384);

    conv_kernel<64, true><<<2048, 128>>>(t1, w2 + 4096, aff + 384, t2);
    stats1_kernel<<<256, 256>>>(t2, ps, pq);
    statsfin_kernel<<<1, 64>>>(ps, pq, g2 + 64, b2 + 64, aff + 512);

    finalmax_kernel<<<2048, 256>>>(t2, x1, aff + 512, out + NB*3*NS);
}

// round 5
// speedup vs baseline: 1.1377x; 1.1377x over previous
#include <cuda_runtime.h>
#include <cstdint>

#define NPTS 8192
#define NS   2048
#define NK   32
#define NB   4
#define MPB  65536              /* NK*NS per batch */
#define FSZ  (NB*64*MPB)        /* 16.7M floats per feature buffer */

__device__ float g_y0[FSZ];
__device__ float g_t1[FSZ];
__device__ float g_t2[FSZ];
__device__ float g_x1[FSZ];
__device__ float g_nxyz[NB*NS*3];
__device__ int   g_idx[NB*NK*NS];
__device__ float g_ps[256];
__device__ float g_pq[256];
__device__ float g_aff[5*128];

static __device__ __forceinline__ unsigned long long pk2(float lo, float hi){
    unsigned long long r; asm("mov.b64 %0,{%1,%2};" : "=l"(r) : "f"(lo), "f"(hi)); return r;
}
static __device__ __forceinline__ void upk2(unsigned long long v, float& lo, float& hi){
    asm("mov.b64 {%0,%1},%2;" : "=f"(lo), "=f"(hi) : "l"(v));
}
static __device__ __forceinline__ void upk2u(unsigned long long v, unsigned& lo, unsigned& hi){
    asm("mov.b64 {%0,%1},%2;" : "=r"(lo), "=r"(hi) : "l"(v));
}
static __device__ __forceinline__ unsigned long long f2fma(unsigned long long a, unsigned long long b, unsigned long long c){
    unsigned long long r; asm("fma.rn.f32x2 %0,%1,%2,%3;" : "=l"(r) : "l"(a), "l"(b), "l"(c)); return r;
}
static __device__ __forceinline__ unsigned long long f2mul(unsigned long long a, unsigned long long b){
    unsigned long long r; asm("mul.rn.f32x2 %0,%1,%2;" : "=l"(r) : "l"(a), "l"(b)); return r;
}
static __device__ __forceinline__ unsigned long long f2add(unsigned long long a, unsigned long long b){
    unsigned long long r; asm("add.rn.f32x2 %0,%1,%2;" : "=l"(r) : "l"(a), "l"(b)); return r;
}
static __device__ __forceinline__ unsigned long long f2sub(unsigned long long a, unsigned long long b){
    unsigned long long r; asm("sub.rn.f32x2 %0,%1,%2;" : "=l"(r) : "l"(a), "l"(b)); return r;
}

// ---------------- FPS: one block per batch ----------------
// Hot loop: 8 packed fp ops per 2 points (exact-rounding sub/mul/add chain,
// bit-identical to the passing R1 kernel); running min-dist and block max kept
// as uint bit patterns on the ALU pipe (monotonic for nonneg floats).
// Argmax index search deferred to the 1-2 threads matching the block max
// (first-occurrence preserved via lo-before-hi overwrite + atomicMin).
extern __shared__ float4 spts[];

__global__ __launch_bounds__(1024, 1) void fps_kernel(const float* __restrict__ xyz,
                                                      float* __restrict__ outxyz,
                                                      float* __restrict__ nxyz)
{
    int b = blockIdx.x, tid = threadIdx.x;
    int lane = tid & 31, wid = tid >> 5;
    const float* X = xyz + (size_t)b * 3 * NPTS;

    __shared__ unsigned swm[32];
    __shared__ unsigned sgm;
    __shared__ int swin[2];

    unsigned long long x2[4], y2[4], z2[4];
    unsigned dist[8];                          // float bit patterns
#pragma unroll
    for (int p = 0; p < 4; ++p) {
        int na = tid + (2*p)   * 1024;
        int nb = tid + (2*p+1) * 1024;
        float xa = X[na],        xbv = X[nb];
        float ya = X[NPTS+na],   yb  = X[NPTS+nb];
        float za = X[2*NPTS+na], zb  = X[2*NPTS+nb];
        x2[p] = pk2(xa, xbv); y2[p] = pk2(ya, yb); z2[p] = pk2(za, zb);
        spts[na] = make_float4(xa, ya, za, 0.f);
        spts[nb] = make_float4(xbv, yb, zb, 0.f);
        dist[2*p] = __float_as_uint(1e10f); dist[2*p+1] = __float_as_uint(1e10f);
    }
    if (tid < 2) swin[tid] = 0x7fffffff;
    __syncthreads();

    float4 c0 = spts[0];
    float cx = c0.x, cy = c0.y, cz = c0.z;

    for (int it = 0; it < NS; ++it) {
        if (tid == 0) {
            outxyz[(b*3 + 0)*NS + it] = cx;
            outxyz[(b*3 + 1)*NS + it] = cy;
            outxyz[(b*3 + 2)*NS + it] = cz;
            nxyz[((size_t)b*NS + it)*3 + 0] = cx;
            nxyz[((size_t)b*NS + it)*3 + 1] = cy;
            nxyz[((size_t)b*NS + it)*3 + 2] = cz;
        }
        unsigned long long cx2 = pk2(cx, cx);
        unsigned long long cy2 = pk2(cy, cy);
        unsigned long long cz2 = pk2(cz, cz);

#pragma unroll
        for (int p = 0; p < 4; ++p) {
            unsigned long long dx = f2sub(x2[p], cx2);
            unsigned long long dy = f2sub(y2[p], cy2);
            unsigned long long dz = f2sub(z2[p], cz2);
            // (dx*dx + dy*dy) + dz*dz -- lane-wise identical to scalar mul/add rounding
            unsigned long long s = f2add(f2add(f2mul(dx, dx), f2mul(dy, dy)), f2mul(dz, dz));
            unsigned slo, shi; upk2u(s, slo, shi);
            dist[2*p]   = min(dist[2*p],   slo);   // uint min == float min (nonneg)
            dist[2*p+1] = min(dist[2*p+1], shi);
        }
        unsigned m01 = max(dist[0], dist[1]), m23 = max(dist[2], dist[3]);
        unsigned m45 = max(dist[4], dist[5]), m67 = max(dist[6], dist[7]);
        unsigned key = max(max(m01, m23), max(m45, m67));

        unsigned kmax = __reduce_max_sync(0xffffffffu, key);
        if (lane == 0) swm[wid] = kmax;
        __syncthreads();                               // b1
        if (wid == 0) {
            unsigned g = __reduce_max_sync(0xffffffffu, swm[lane]);
            if (lane == 0) { sgm = g; swin[(it + 1) & 1] = 0x7fffffff; }
        }
        __syncthreads();                               // b2
        unsigned g = sgm;
        if (key == g) {                                // rare: 1-2 threads
            int li = 0x7fffffff;
#pragma unroll
            for (int p = 3; p >= 0; --p) {             // lo overwrites hi -> first occurrence
                if (dist[2*p+1] == g) li = tid + (2*p+1) * 1024;
                if (dist[2*p]   == g) li = tid + (2*p)   * 1024;
            }
            atomicMin(&swin[it & 1], li);              // min over threads -> global first
        }
        __syncthreads();                               // b3
        float4 cc = spts[swin[it & 1]];
        cx = cc.x; cy = cc.y; cz = cc.z;
    }
}

// ---------------- ball query: one warp per center ----------------
__global__ __launch_bounds__(256) void ball_kernel(const float* __restrict__ xyz,
                                                   const float* __restrict__ nxyz,
                                                   int* __restrict__ gidx)
{
    __shared__ int sbuf[8][32];
    int w = threadIdx.x >> 5, lane = threadIdx.x & 31;
    int gid = blockIdx.x * 8 + w;              // B*S = 8192 centers
    int b = gid >> 11, s = gid & 2047;
    const float* X = xyz + (size_t)b * 3 * NPTS;

    float cx = nxyz[gid*3], cy = nxyz[gid*3 + 1], cz = nxyz[gid*3 + 2];
    float cc = __fadd_rn(__fadd_rn(__fmul_rn(cx,cx), __fmul_rn(cy,cy)), __fmul_rn(cz,cz));
    const float R2 = (float)(0.1 * 0.1);

    int cnt = 0;
    for (int base = 0; base < NPTS; base += 32) {
        int n = base + lane;
        float px = X[n], py = X[NPTS + n], pz = X[2*NPTS + n];
        float pp  = __fadd_rn(__fadd_rn(__fmul_rn(px,px), __fmul_rn(py,py)), __fmul_rn(pz,pz));
        float dot = __fadd_rn(__fadd_rn(__fmul_rn(cx,px), __fmul_rn(cy,py)), __fmul_rn(cz,pz));
        float sqr = __fadd_rn(__fadd_rn(cc, pp), -__fmul_rn(2.f, dot));
        bool hit = (sqr <= R2);
        unsigned m = __ballot_sync(0xffffffffu, hit);
        if (m) {
            int rank = cnt + __popc(m & ((1u << lane) - 1u));
            if (hit && rank < 32) sbuf[w][rank] = n;
            cnt += __popc(m);
            if (cnt >= 32) break;
        }
    }
    __syncwarp();
    int first = sbuf[w][0];                    // center always in-radius -> cnt >= 1
    int my = (lane < cnt) ? sbuf[w][lane] : first;
    gidx[((size_t)(b*32 + lane))*2048 + s] = my;
}

// ---------------- gather + center-subtract + concat ----------------
__global__ __launch_bounds__(256) void gather_kernel(const float* __restrict__ xyz,
                                                     const float* __restrict__ pts,
                                                     const int* __restrict__ gidx,
                                                     const float* __restrict__ nxyz,
                                                     float* __restrict__ xin)
{
    int g = blockIdx.x * 256 + threadIdx.x;    // 262144 (b,k,s)
    int s = g & 2047, k = (g >> 11) & 31, b = g >> 16;
    int id = gidx[((size_t)(b*32 + k))*2048 + s];
    const float* X = xyz + (size_t)b * 3 * NPTS;
    const float* P = pts + (size_t)b * 29 * NPTS;
    size_t ob = (size_t)b * 32 * MPB + (size_t)k * 2048 + s;
#pragma unroll
    for (int c = 0; c < 3; ++c)
        xin[ob + (size_t)c * MPB] = X[c*NPTS + id] - nxyz[((size_t)(b*2048 + s))*3 + c];
#pragma unroll
    for (int c = 0; c < 29; ++c)
        xin[ob + (size_t)(3 + c) * MPB] = P[c*NPTS + id];
}

// ---------------- conv: out[b][o][m] = sum_c W[o][c] * act(in[b][c][m]) ----------------
template<int CIN, bool ACT>
__global__ __launch_bounds__(128) void conv_kernel(const float* __restrict__ in,
                                                   const float* __restrict__ W,
                                                   const float* __restrict__ aff,
                                                   float* __restrict__ out)
{
    __shared__ float sW[CIN][64];
    __shared__ float sA[64], sD[64];
    int tid = threadIdx.x;
    for (int i = tid; i < CIN * 64; i += 128)
        sW[i >> 6][i & 63] = W[(i & 63) * CIN + (i >> 6)];
    if (ACT && tid < CIN) { sA[tid] = aff[tid]; sD[tid] = aff[64 + tid]; }
    __syncthreads();

    int b = blockIdx.x >> 9;
    int m = ((blockIdx.x & 511) << 7) + ((tid & 31) << 2);
    int og = (tid >> 5) << 4;                  // 16 outputs per thread
    const float* ip = in + (size_t)b * CIN * MPB + m;

    unsigned long long acc[8][4];
#pragma unroll
    for (int p = 0; p < 8; ++p)
#pragma unroll
        for (int j = 0; j < 4; ++j) acc[p][j] = 0ull;

    float4 xv = *(const float4*)(ip);          // prefetch c=0
#pragma unroll 8
    for (int c = 0; c < CIN; ++c) {
        float4 xn;
        if (c + 1 < CIN) xn = *(const float4*)(ip + (size_t)(c + 1) * MPB);
        float4 x = xv;
        if (ACT) {
            float a = sA[c], d = sD[c];
            x.x = fmaxf(fmaf(a, x.x, d), 0.f);
            x.y = fmaxf(fmaf(a, x.y, d), 0.f);
            x.z = fmaxf(fmaf(a, x.z, d), 0.f);
            x.w = fmaxf(fmaf(a, x.w, d), 0.f);
        }
        unsigned long long xp[4] = { pk2(x.x, x.x), pk2(x.y, x.y),
                                     pk2(x.z, x.z), pk2(x.w, x.w) };
        const double2* wp = (const double2*)&sW[c][og];
        double2 w0 = wp[0], w1 = wp[1], w2 = wp[2], w3 = wp[3];
        unsigned long long wq[8] = {
            __double_as_longlong(w0.x), __double_as_longlong(w0.y),
            __double_as_longlong(w1.x), __double_as_longlong(w1.y),
            __double_as_longlong(w2.x), __double_as_longlong(w2.y),
            __double_as_longlong(w3.x), __double_as_longlong(w3.y) };
#pragma unroll
        for (int p = 0; p < 8; ++p)
#pragma unroll
            for (int j = 0; j < 4; ++j)
                acc[p][j] = f2fma(wq[p], xp[j], acc[p][j]);
        xv = xn;
    }

    float* op = out + (size_t)b * 64 * MPB + m;
#pragma unroll
    for (int p = 0; p < 8; ++p)
#pragma unroll
        for (int j = 0; j < 4; ++j) {
            float lo, hi; upk2(acc[p][j], lo, hi);
            op[(size_t)(og + 2*p)     * MPB + j] = lo;
            op[(size_t)(og + 2*p + 1) * MPB + j] = hi;
        }
}

// ---------------- per-channel stats (two-stage, deterministic) ----------------
__global__ __launch_bounds__(256) void stats1_kernel(const float* __restrict__ in,
                                                     float* __restrict__ ps,
                                                     float* __restrict__ pq)
{
    int o = blockIdx.x >> 2, b = blockIdx.x & 3;
    const float4* p = (const float4*)(in + (size_t)(b*64 + o) * MPB);
    float s = 0.f, q = 0.f;
    for (int i = threadIdx.x; i < MPB/4; i += 256) {
        float4 v = p[i];
        s += v.x + v.y + v.z + v.w;
        q += v.x*v.x + v.y*v.y + v.z*v.z + v.w*v.w;
    }
    __shared__ float rs[256], rq[256];
    rs[threadIdx.x] = s; rq[threadIdx.x] = q;
    for (int off = 128; off; off >>= 1) {
        __syncthreads();
        if (threadIdx.x < off) { rs[threadIdx.x] += rs[threadIdx.x + off];
                                 rq[threadIdx.x] += rq[threadIdx.x + off]; }
    }
    if (threadIdx.x == 0) { ps[blockIdx.x] = rs[0]; pq[blockIdx.x] = rq[0]; }
}

__global__ void statsfin_kernel(const float* __restrict__ ps, const float* __restrict__ pq,
                                const float* __restrict__ gam, const float* __restrict__ bet,
                                float* __restrict__ aff)
{
    int o = threadIdx.x;                       // 64 threads
    float s = ps[o*4] + ps[o*4+1] + ps[o*4+2] + ps[o*4+3];
    float q = pq[o*4] + pq[o*4+1] + pq[o*4+2] + pq[o*4+3];
    const float invn = 1.f / (float)(NB * MPB);
    float mean = s * invn;
    float var  = q * invn - mean * mean;
    float a = gam[o] * rsqrtf(var + 1e-5f);
    aff[o] = a;
    aff[64 + o] = bet[o] - a * mean;
}

// ---------------- residual: x1 = relu(aff2(t2) + relu(aff0(y0))) ----------------
__global__ __launch_bounds__(256) void resid_kernel(const float* __restrict__ y0,
                                                    const float* __restrict__ t2,
                                                    const float* __restrict__ aff0,
                                                    const float* __restrict__ aff2,
                                                    float* __restrict__ x1)
{
    size_t i = (size_t)blockIdx.x * 256 + threadIdx.x;   // float4 index, 4.19M
    int c = (int)((i >> 14) & 63);
    float a0 = aff0[c], d0 = aff0[64+c], a2 = aff2[c], d2 = aff2[64+c];
    float4 y = ((const float4*)y0)[i];
    float4 t = ((const float4*)t2)[i];
    float4 r;
    r.x = fmaxf(fmaf(a2, t.x, d2) + fmaxf(fmaf(a0, y.x, d0), 0.f), 0.f);
    r.y = fmaxf(fmaf(a2, t.y, d2) + fmaxf(fmaf(a0, y.y, d0), 0.f), 0.f);
    r.z = fmaxf(fmaf(a2, t.z, d2) + fmaxf(fmaf(a0, y.z, d0), 0.f), 0.f);
    r.w = fmaxf(fmaf(a2, t.w, d2) + fmaxf(fmaf(a0, y.w, d0), 0.f), 0.f);
    ((float4*)x1)[i] = r;
}

// ---------------- final: feat = max_k relu(aff4(t4) + x1) ----------------
__global__ __launch_bounds__(256) void finalmax_kernel(const float* __restrict__ t4,
                                                       const float* __restrict__ x1,
                                                       const float* __restrict__ aff,
                                                       float* __restrict__ outf)
{
    int g = blockIdx.x * 256 + threadIdx.x;    // 524288 = (b,o,s)
    int s = g & 2047, o = (g >> 11) & 63, b = g >> 17;
    float a = aff[o], d = aff[64 + o];
    size_t base = (size_t)(b*64 + o) * MPB + s;
    const float* tp = t4 + base;
    const float* xp = x1 + base;
    float m = -1e30f;
#pragma unroll 8
    for (int k = 0; k < 32; ++k)
        m = fmaxf(m, fmaf(a, tp[(size_t)k*2048], d) + xp[(size_t)k*2048]);
    outf[g] = fmaxf(m, 0.f);                   // max_k relu == relu(max_k)
}

extern "C" void kernel_launch(void* const* d_in, const int* in_sizes, int n_in,
                              void* d_out, int out_size)
{
    (void)in_sizes; (void)n_in; (void)out_size;
    const float* xyz = (const float*)d_in[0];
    const float* pts = (const float*)d_in[1];
    const float* pw  = (const float*)d_in[2];
    const float* pg  = (const float*)d_in[3];
    const float* pb  = (const float*)d_in[4];
    const float* w1  = (const float*)d_in[5];
    const float* g1  = (const float*)d_in[6];
    const float* b1  = (const float*)d_in[7];
    const float* w2  = (const float*)d_in[8];
    const float* g2  = (const float*)d_in[9];
    const float* b2  = (const float*)d_in[10];

    float *y0, *t1, *t2, *x1, *nx, *ps, *pq, *aff; int* gi;
    cudaGetSymbolAddress((void**)&y0,  g_y0);
    cudaGetSymbolAddress((void**)&t1,  g_t1);
    cudaGetSymbolAddress((void**)&t2,  g_t2);
    cudaGetSymbolAddress((void**)&x1,  g_x1);
    cudaGetSymbolAddress((void**)&nx,  g_nxyz);
    cudaGetSymbolAddress((void**)&gi,  g_idx);
    cudaGetSymbolAddress((void**)&ps,  g_ps);
    cudaGetSymbolAddress((void**)&pq,  g_pq);
    cudaGetSymbolAddress((void**)&aff, g_aff);
    float* out = (float*)d_out;

    cudaFuncSetAttribute(fps_kernel, cudaFuncAttributeMaxDynamicSharedMemorySize,
                         NPTS * (int)sizeof(float4));

    fps_kernel<<<NB, 1024, NPTS * sizeof(float4)>>>(xyz, out, nx);
    ball_kernel<<<1024, 256>>>(xyz, nx, gi);
    gather_kernel<<<1024, 256>>>(xyz, pts, gi, nx, t2);

    conv_kernel<32, false><<<2048, 128>>>(t2, pw, nullptr, y0);
    stats1_kernel<<<256, 256>>>(y0, ps, pq);
    statsfin_kernel<<<1, 64>>>(ps, pq, pg, pb, aff);

    conv_kernel<64, true><<<2048, 128>>>(y0, w1, aff, t1);
    stats1_kernel<<<256, 256>>>(t1, ps, pq);
    statsfin_kernel<<<1, 64>>>(ps, pq, g1, b1, aff + 128);

    conv_kernel<64, true><<<2048, 128>>>(t1, w2, aff + 128, t2);
    stats1_kernel<<<256, 256>>>(t2, ps, pq);
    statsfin_kernel<<<1, 64>>>(ps, pq, g2, b2, aff + 256);

    resid_kernel<<<16384, 256>>>(y0, t2, aff, aff + 256, x1);

    conv_kernel<64, false><<<2048, 128>>>(x1, w1 + 4096, nullptr, t1);
    stats1_kernel<<<256, 256>>>(t1, ps, pq);
    statsfin_kernel<<<1, 64>>>(ps, pq, g1 + 64, b1 + 64, aff + 384);

    conv_kernel<64, true><<<2048, 128>>>(t1, w2 + 4096, aff + 384, t2);
    stats1_kernel<<<256, 256>>>(t2, ps, pq);
    statsfin_kernel<<<1, 64>>>(ps, pq, g2 + 64, b2 + 64, aff + 512);

    finalmax_kernel<<<2048, 256>>>(t2, x1, aff + 512, out + NB*3*NS);
}

// round 6
// speedup vs baseline: 1.2255x; 1.0772x over previous
#include <cuda_runtime.h>
#include <cstdint>

#define NPTS 8192
#define NS   2048
#define NK   32
#define NB   4
#define MPB  65536              /* NK*NS per batch */
#define FSZ  (NB*64*MPB)        /* 16.7M floats per feature buffer */

__device__ float g_y0[FSZ];
__device__ float g_t1[FSZ];
__device__ float g_t2[FSZ];
__device__ float g_x1[FSZ];
__device__ float g_nxyz[NB*NS*3];
__device__ int   g_idx[NB*NK*NS];
__device__ float g_ps[64*2048];
__device__ float g_pq[64*2048];
__device__ float g_aff[5*128];

static __device__ __forceinline__ unsigned long long pk2(float lo, float hi){
    unsigned long long r; asm("mov.b64 %0,{%1,%2};" : "=l"(r) : "f"(lo), "f"(hi)); return r;
}
static __device__ __forceinline__ void upk2(unsigned long long v, float& lo, float& hi){
    asm("mov.b64 {%0,%1},%2;" : "=f"(lo), "=f"(hi) : "l"(v));
}
static __device__ __forceinline__ void upk2u(unsigned long long v, unsigned& lo, unsigned& hi){
    asm("mov.b64 {%0,%1},%2;" : "=r"(lo), "=r"(hi) : "l"(v));
}
static __device__ __forceinline__ unsigned long long f2fma(unsigned long long a, unsigned long long b, unsigned long long c){
    unsigned long long r; asm("fma.rn.f32x2 %0,%1,%2,%3;" : "=l"(r) : "l"(a), "l"(b), "l"(c)); return r;
}
static __device__ __forceinline__ unsigned long long f2mul(unsigned long long a, unsigned long long b){
    unsigned long long r; asm("mul.rn.f32x2 %0,%1,%2;" : "=l"(r) : "l"(a), "l"(b)); return r;
}
static __device__ __forceinline__ unsigned long long f2add(unsigned long long a, unsigned long long b){
    unsigned long long r; asm("add.rn.f32x2 %0,%1,%2;" : "=l"(r) : "l"(a), "l"(b)); return r;
}
static __device__ __forceinline__ unsigned long long f2sub(unsigned long long a, unsigned long long b){
    unsigned long long r; asm("sub.rn.f32x2 %0,%1,%2;" : "=l"(r) : "l"(a), "l"(b)); return r;
}

// ---------------- FPS: one block per batch (unchanged from R4 pass) ----------------
extern __shared__ float4 spts[];

__global__ __launch_bounds__(1024, 1) void fps_kernel(const float* __restrict__ xyz,
                                                      float* __restrict__ outxyz,
                                                      float* __restrict__ nxyz)
{
    int b = blockIdx.x, tid = threadIdx.x;
    int lane = tid & 31, wid = tid >> 5;
    const float* X = xyz + (size_t)b * 3 * NPTS;

    __shared__ unsigned swm[32];
    __shared__ unsigned sgm;
    __shared__ int swin[2];

    unsigned long long x2[4], y2[4], z2[4];
    unsigned dist[8];
#pragma unroll
    for (int p = 0; p < 4; ++p) {
        int na = tid + (2*p)   * 1024;
        int nb = tid + (2*p+1) * 1024;
        float xa = X[na],        xbv = X[nb];
        float ya = X[NPTS+na],   yb  = X[NPTS+nb];
        float za = X[2*NPTS+na], zb  = X[2*NPTS+nb];
        x2[p] = pk2(xa, xbv); y2[p] = pk2(ya, yb); z2[p] = pk2(za, zb);
        spts[na] = make_float4(xa, ya, za, 0.f);
        spts[nb] = make_float4(xbv, yb, zb, 0.f);
        dist[2*p] = __float_as_uint(1e10f); dist[2*p+1] = __float_as_uint(1e10f);
    }
    if (tid < 2) swin[tid] = 0x7fffffff;
    __syncthreads();

    float4 c0 = spts[0];
    float cx = c0.x, cy = c0.y, cz = c0.z;

    for (int it = 0; it < NS; ++it) {
        if (tid == 0) {
            outxyz[(b*3 + 0)*NS + it] = cx;
            outxyz[(b*3 + 1)*NS + it] = cy;
            outxyz[(b*3 + 2)*NS + it] = cz;
            nxyz[((size_t)b*NS + it)*3 + 0] = cx;
            nxyz[((size_t)b*NS + it)*3 + 1] = cy;
            nxyz[((size_t)b*NS + it)*3 + 2] = cz;
        }
        unsigned long long cx2 = pk2(cx, cx);
        unsigned long long cy2 = pk2(cy, cy);
        unsigned long long cz2 = pk2(cz, cz);

#pragma unroll
        for (int p = 0; p < 4; ++p) {
            unsigned long long dx = f2sub(x2[p], cx2);
            unsigned long long dy = f2sub(y2[p], cy2);
            unsigned long long dz = f2sub(z2[p], cz2);
            unsigned long long s = f2add(f2add(f2mul(dx, dx), f2mul(dy, dy)), f2mul(dz, dz));
            unsigned slo, shi; upk2u(s, slo, shi);
            dist[2*p]   = min(dist[2*p],   slo);
            dist[2*p+1] = min(dist[2*p+1], shi);
        }
        unsigned m01 = max(dist[0], dist[1]), m23 = max(dist[2], dist[3]);
        unsigned m45 = max(dist[4], dist[5]), m67 = max(dist[6], dist[7]);
        unsigned key = max(max(m01, m23), max(m45, m67));

        unsigned kmax = __reduce_max_sync(0xffffffffu, key);
        if (lane == 0) swm[wid] = kmax;
        __syncthreads();
        if (wid == 0) {
            unsigned g = __reduce_max_sync(0xffffffffu, swm[lane]);
            if (lane == 0) { sgm = g; swin[(it + 1) & 1] = 0x7fffffff; }
        }
        __syncthreads();
        unsigned g = sgm;
        if (key == g) {
            int li = 0x7fffffff;
#pragma unroll
            for (int p = 3; p >= 0; --p) {
                if (dist[2*p+1] == g) li = tid + (2*p+1) * 1024;
                if (dist[2*p]   == g) li = tid + (2*p)   * 1024;
            }
            atomicMin(&swin[it & 1], li);
        }
        __syncthreads();
        float4 cc = spts[swin[it & 1]];
        cx = cc.x; cy = cc.y; cz = cc.z;
    }
}

// ---------------- ball query: one warp per center ----------------
__global__ __launch_bounds__(256) void ball_kernel(const float* __restrict__ xyz,
                                                   const float* __restrict__ nxyz,
                                                   int* __restrict__ gidx)
{
    __shared__ int sbuf[8][32];
    int w = threadIdx.x >> 5, lane = threadIdx.x & 31;
    int gid = blockIdx.x * 8 + w;
    int b = gid >> 11, s = gid & 2047;
    const float* X = xyz + (size_t)b * 3 * NPTS;

    float cx = nxyz[gid*3], cy = nxyz[gid*3 + 1], cz = nxyz[gid*3 + 2];
    float cc = __fadd_rn(__fadd_rn(__fmul_rn(cx,cx), __fmul_rn(cy,cy)), __fmul_rn(cz,cz));
    const float R2 = (float)(0.1 * 0.1);

    int cnt = 0;
    for (int base = 0; base < NPTS; base += 32) {
        int n = base + lane;
        float px = X[n], py = X[NPTS + n], pz = X[2*NPTS + n];
        float pp  = __fadd_rn(__fadd_rn(__fmul_rn(px,px), __fmul_rn(py,py)), __fmul_rn(pz,pz));
        float dot = __fadd_rn(__fadd_rn(__fmul_rn(cx,px), __fmul_rn(cy,py)), __fmul_rn(cz,pz));
        float sqr = __fadd_rn(__fadd_rn(cc, pp), -__fmul_rn(2.f, dot));
        bool hit = (sqr <= R2);
        unsigned m = __ballot_sync(0xffffffffu, hit);
        if (m) {
            int rank = cnt + __popc(m & ((1u << lane) - 1u));
            if (hit && rank < 32) sbuf[w][rank] = n;
            cnt += __popc(m);
            if (cnt >= 32) break;
        }
    }
    __syncwarp();
    int first = sbuf[w][0];
    int my = (lane < cnt) ? sbuf[w][lane] : first;
    gidx[((size_t)(b*32 + lane))*2048 + s] = my;
}

// ---------------- gather + center-subtract + concat ----------------
__global__ __launch_bounds__(256) void gather_kernel(const float* __restrict__ xyz,
                                                     const float* __restrict__ pts,
                                                     const int* __restrict__ gidx,
                                                     const float* __restrict__ nxyz,
                                                     float* __restrict__ xin)
{
    int g = blockIdx.x * 256 + threadIdx.x;
    int s = g & 2047, k = (g >> 11) & 31, b = g >> 16;
    int id = gidx[((size_t)(b*32 + k))*2048 + s];
    const float* X = xyz + (size_t)b * 3 * NPTS;
    const float* P = pts + (size_t)b * 29 * NPTS;
    size_t ob = (size_t)b * 32 * MPB + (size_t)k * 2048 + s;
#pragma unroll
    for (int c = 0; c < 3; ++c)
        xin[ob + (size_t)c * MPB] = X[c*NPTS + id] - nxyz[((size_t)(b*2048 + s))*3 + c];
#pragma unroll
    for (int c = 0; c < 29; ++c)
        xin[ob + (size_t)(3 + c) * MPB] = P[c*NPTS + id];
}

// ---------------- conv v2: smem-staged input, 256 thr, fused stats ----------------
// out[b][o][m] = sum_c W[o][c] * act(in[b][c][m]); per-block per-out partial
// sums/sumsq written to ps/pq (stage 2 = statsfin2).
template<int CIN, bool ACT>
__global__ __launch_bounds__(256) void conv_kernel(const float* __restrict__ in,
                                                   const float* __restrict__ W,
                                                   const float* __restrict__ aff,
                                                   float* __restrict__ out,
                                                   float* __restrict__ ps,
                                                   float* __restrict__ pq)
{
    constexpr int CH = CIN / 8;                // channel chunks of 8
    __shared__ float sW[CIN][64];
    __shared__ float sX[2][8][128];
    __shared__ float sA[64], sD[64];
    int tid = threadIdx.x, lane = tid & 31, w = tid >> 5;
    int b = blockIdx.x >> 9, mblk = blockIdx.x & 511;
    const float* ip = in + (size_t)b * CIN * MPB + mblk * 128 + lane * 4;

    for (int i = tid; i < CIN * 64; i += 256)
        sW[i >> 6][i & 63] = W[(i & 63) * CIN + (i >> 6)];
    if (ACT) for (int i = tid; i < CIN; i += 256) { sA[i] = aff[i]; sD[i] = aff[64 + i]; }

    float4 xr0 = *(const float4*)(ip + (size_t)w * MPB);             // chunk 0, ch w
    float4 xr  = (CH > 1) ? *(const float4*)(ip + (size_t)(8 + w) * MPB) : xr0;
    __syncthreads();                            // sW/sA visible
    {
        float4 v = xr0;
        if (ACT) { float a = sA[w], d = sD[w];
            v.x = fmaxf(fmaf(a, v.x, d), 0.f); v.y = fmaxf(fmaf(a, v.y, d), 0.f);
            v.z = fmaxf(fmaf(a, v.z, d), 0.f); v.w = fmaxf(fmaf(a, v.w, d), 0.f); }
        *(float4*)&sX[0][w][lane * 4] = v;
    }
    __syncthreads();                            // sX[0] ready

    int og = w * 8;                             // 8 outputs per thread
    unsigned long long acc[4][4];
#pragma unroll
    for (int p = 0; p < 4; ++p)
#pragma unroll
        for (int j = 0; j < 4; ++j) acc[p][j] = 0ull;

    for (int k = 0; k < CH; ++k) {
#pragma unroll
        for (int cc = 0; cc < 8; ++cc) {
            int c = k * 8 + cc;
            float4 x = *(const float4*)&sX[k & 1][cc][lane * 4];
            unsigned long long xp[4] = { pk2(x.x, x.x), pk2(x.y, x.y),
                                         pk2(x.z, x.z), pk2(x.w, x.w) };
            const double2* wp = (const double2*)&sW[c][og];
            double2 w0 = wp[0], w1 = wp[1];
            unsigned long long wq[4] = {
                __double_as_longlong(w0.x), __double_as_longlong(w0.y),
                __double_as_longlong(w1.x), __double_as_longlong(w1.y) };
#pragma unroll
            for (int p = 0; p < 4; ++p)
#pragma unroll
                for (int j = 0; j < 4; ++j)
                    acc[p][j] = f2fma(wq[p], xp[j], acc[p][j]);
        }
        if (k + 1 < CH) {
            float4 v = xr;
            if (ACT) { int ch = (k + 1) * 8 + w; float a = sA[ch], d = sD[ch];
                v.x = fmaxf(fmaf(a, v.x, d), 0.f); v.y = fmaxf(fmaf(a, v.y, d), 0.f);
                v.z = fmaxf(fmaf(a, v.z, d), 0.f); v.w = fmaxf(fmaf(a, v.w, d), 0.f); }
            *(float4*)&sX[(k + 1) & 1][w][lane * 4] = v;
            if (k + 2 < CH) xr = *(const float4*)(ip + (size_t)((k + 2) * 8 + w) * MPB);
        }
        __syncthreads();
    }

    // write outputs + fused per-block stats partials
    float* op = out + (size_t)b * 64 * MPB + mblk * 128 + lane * 4;
    int pblk = b * 512 + mblk;
#pragma unroll
    for (int p = 0; p < 4; ++p) {
        float4 vlo, vhi;
        upk2(acc[p][0], vlo.x, vhi.x); upk2(acc[p][1], vlo.y, vhi.y);
        upk2(acc[p][2], vlo.z, vhi.z); upk2(acc[p][3], vlo.w, vhi.w);
        *(float4*)(op + (size_t)(og + 2*p)     * MPB) = vlo;
        *(float4*)(op + (size_t)(og + 2*p + 1) * MPB) = vhi;
        float sl = vlo.x + vlo.y + vlo.z + vlo.w;
        float ql = vlo.x*vlo.x + vlo.y*vlo.y + vlo.z*vlo.z + vlo.w*vlo.w;
        float sh = vhi.x + vhi.y + vhi.z + vhi.w;
        float qh = vhi.x*vhi.x + vhi.y*vhi.y + vhi.z*vhi.z + vhi.w*vhi.w;
#pragma unroll
        for (int off = 16; off; off >>= 1) {
            sl += __shfl_xor_sync(0xffffffffu, sl, off);
            ql += __shfl_xor_sync(0xffffffffu, ql, off);
            sh += __shfl_xor_sync(0xffffffffu, sh, off);
            qh += __shfl_xor_sync(0xffffffffu, qh, off);
        }
        if (lane == 0) {
            ps[(og + 2*p)     * 2048 + pblk] = sl;
            pq[(og + 2*p)     * 2048 + pblk] = ql;
            ps[(og + 2*p + 1) * 2048 + pblk] = sh;
            pq[(og + 2*p + 1) * 2048 + pblk] = qh;
        }
    }
}

// ---------------- stage-2 stats: 2048 partials -> affine coeffs ----------------
__global__ __launch_bounds__(256) void statsfin2_kernel(const float* __restrict__ ps,
                                                        const float* __restrict__ pq,
                                                        const float* __restrict__ gam,
                                                        const float* __restrict__ bet,
                                                        float* __restrict__ aff)
{
    int o = blockIdx.x, tid = threadIdx.x;
    float s = 0.f, q = 0.f;
    for (int i = tid; i < 2048; i += 256) { s += ps[o*2048 + i]; q += pq[o*2048 + i]; }
    __shared__ float rs[256], rq[256];
    rs[tid] = s; rq[tid] = q;
    for (int off = 128; off; off >>= 1) {
        __syncthreads();
        if (tid < off) { rs[tid] += rs[tid + off]; rq[tid] += rq[tid + off]; }
    }
    if (tid == 0) {
        const float invn = 1.f / (float)(NB * MPB);
        float mean = rs[0] * invn;
        float var  = rq[0] * invn - mean * mean;
        float a = gam[o] * rsqrtf(var + 1e-5f);
        aff[o] = a;
        aff[64 + o] = bet[o] - a * mean;
    }
}

// ---------------- residual: x1 = relu(aff2(t2) + relu(aff0(y0))) ----------------
__global__ __launch_bounds__(256) void resid_kernel(const float* __restrict__ y0,
                                                    const float* __restrict__ t2,
                                                    const float* __restrict__ aff0,
                                                    const float* __restrict__ aff2,
                                                    float* __restrict__ x1)
{
    size_t i = (size_t)blockIdx.x * 256 + threadIdx.x;
    int c = (int)((i >> 14) & 63);
    float a0 = aff0[c], d0 = aff0[64+c], a2 = aff2[c], d2 = aff2[64+c];
    float4 y = ((const float4*)y0)[i];
    float4 t = ((const float4*)t2)[i];
    float4 r;
    r.x = fmaxf(fmaf(a2, t.x, d2) + fmaxf(fmaf(a0, y.x, d0), 0.f), 0.f);
    r.y = fmaxf(fmaf(a2, t.y, d2) + fmaxf(fmaf(a0, y.y, d0), 0.f), 0.f);
    r.z = fmaxf(fmaf(a2, t.z, d2) + fmaxf(fmaf(a0, y.z, d0), 0.f), 0.f);
    r.w = fmaxf(fmaf(a2, t.w, d2) + fmaxf(fmaf(a0, y.w, d0), 0.f), 0.f);
    ((float4*)x1)[i] = r;
}

// ---------------- final: feat = max_k relu(aff4(t4) + x1) ----------------
__global__ __launch_bounds__(256) void finalmax_kernel(const float* __restrict__ t4,
                                                       const float* __restrict__ x1,
                                                       const float* __restrict__ aff,
                                                       float* __restrict__ outf)
{
    int g = blockIdx.x * 256 + threadIdx.x;
    int s = g & 2047, o = (g >> 11) & 63, b = g >> 17;
    float a = aff[o], d = aff[64 + o];
    size_t base = (size_t)(b*64 + o) * MPB + s;
    const float* tp = t4 + base;
    const float* xp = x1 + base;
    float m = -1e30f;
#pragma unroll 8
    for (int k = 0; k < 32; ++k)
        m = fmaxf(m, fmaf(a, tp[(size_t)k*2048], d) + xp[(size_t)k*2048]);
    outf[g] = fmaxf(m, 0.f);
}

extern "C" void kernel_launch(void* const* d_in, const int* in_sizes, int n_in,
                              void* d_out, int out_size)
{
    (void)in_sizes; (void)n_in; (void)out_size;
    const float* xyz = (const float*)d_in[0];
    const float* pts = (const float*)d_in[1];
    const float* pw  = (const float*)d_in[2];
    const float* pg  = (const float*)d_in[3];
    const float* pb  = (const float*)d_in[4];
    const float* w1  = (const float*)d_in[5];
    const float* g1  = (const float*)d_in[6];
    const float* b1  = (const float*)d_in[7];
    const float* w2  = (const float*)d_in[8];
    const float* g2  = (const float*)d_in[9];
    const float* b2  = (const float*)d_in[10];

    float *y0, *t1, *t2, *x1, *nx, *ps, *pq, *aff; int* gi;
    cudaGetSymbolAddress((void**)&y0,  g_y0);
    cudaGetSymbolAddress((void**)&t1,  g_t1);
    cudaGetSymbolAddress((void**)&t2,  g_t2);
    cudaGetSymbolAddress((void**)&x1,  g_x1);
    cudaGetSymbolAddress((void**)&nx,  g_nxyz);
    cudaGetSymbolAddress((void**)&gi,  g_idx);
    cudaGetSymbolAddress((void**)&ps,  g_ps);
    cudaGetSymbolAddress((void**)&pq,  g_pq);
    cudaGetSymbolAddress((void**)&aff, g_aff);
    float* out = (float*)d_out;

    cudaFuncSetAttribute(fps_kernel, cudaFuncAttributeMaxDynamicSharedMemorySize,
                         NPTS * (int)sizeof(float4));

    fps_kernel<<<NB, 1024, NPTS * sizeof(float4)>>>(xyz, out, nx);
    ball_kernel<<<1024, 256>>>(xyz, nx, gi);
    gather_kernel<<<1024, 256>>>(xyz, pts, gi, nx, t2);

    conv_kernel<32, false><<<2048, 256>>>(t2, pw, nullptr, y0, ps, pq);
    statsfin2_kernel<<<64, 256>>>(ps, pq, pg, pb, aff);

    conv_kernel<64, true><<<2048, 256>>>(y0, w1, aff, t1, ps, pq);
    statsfin2_kernel<<<64, 256>>>(ps, pq, g1, b1, aff + 128);

    conv_kernel<64, true><<<2048, 256>>>(t1, w2, aff + 128, t2, ps, pq);
    statsfin2_kernel<<<64, 256>>>(ps, pq, g2, b2, aff + 256);

    resid_kernel<<<16384, 256>>>(y0, t2, aff, aff + 256, x1);

    conv_kernel<64, false><<<2048, 256>>>(x1, w1 + 4096, nullptr, t1, ps, pq);
    statsfin2_kernel<<<64, 256>>>(ps, pq, g1 + 64, b1 + 64, aff + 384);

    conv_kernel<64, true><<<2048, 256>>>(t1, w2 + 4096, aff + 384, t2, ps, pq);
    statsfin2_kernel<<<64, 256>>>(ps, pq, g2 + 64, b2 + 64, aff + 512);

    finalmax_kernel<<<2048, 256>>>(t2, x1, aff + 512, out + NB*3*NS);
}

// round 7
// speedup vs baseline: 1.4104x; 1.1509x over previous
#include <cuda_runtime.h>
#include <cstdint>

#define NPTS 8192
#define NS   2048
#define NK   32
#define NB   4
#define MPB  65536              /* NK*NS per batch */
#define FSZ  (NB*64*MPB)        /* 16.7M floats per feature buffer */

__device__ float g_y0[FSZ];
__device__ float g_t1[FSZ];
__device__ float g_t2[FSZ];
__device__ float g_x1[FSZ];
__device__ float g_nxyz[NB*NS*3];
__device__ int   g_idx[NB*NK*NS];
__device__ float g_ps[64*2048];
__device__ float g_pq[64*2048];
__device__ float g_aff[5*128];

static __device__ __forceinline__ unsigned long long pk2(float lo, float hi){
    unsigned long long r; asm("mov.b64 %0,{%1,%2};" : "=l"(r) : "f"(lo), "f"(hi)); return r;
}
static __device__ __forceinline__ void upk2(unsigned long long v, float& lo, float& hi){
    asm("mov.b64 {%0,%1},%2;" : "=f"(lo), "=f"(hi) : "l"(v));
}
static __device__ __forceinline__ void upk2u(unsigned long long v, unsigned& lo, unsigned& hi){
    asm("mov.b64 {%0,%1},%2;" : "=r"(lo), "=r"(hi) : "l"(v));
}
static __device__ __forceinline__ unsigned long long f2fma(unsigned long long a, unsigned long long b, unsigned long long c){
    unsigned long long r; asm("fma.rn.f32x2 %0,%1,%2,%3;" : "=l"(r) : "l"(a), "l"(b), "l"(c)); return r;
}
static __device__ __forceinline__ unsigned long long f2mul(unsigned long long a, unsigned long long b){
    unsigned long long r; asm("mul.rn.f32x2 %0,%1,%2;" : "=l"(r) : "l"(a), "l"(b)); return r;
}
static __device__ __forceinline__ unsigned long long f2add(unsigned long long a, unsigned long long b){
    unsigned long long r; asm("add.rn.f32x2 %0,%1,%2;" : "=l"(r) : "l"(a), "l"(b)); return r;
}
static __device__ __forceinline__ unsigned long long f2sub(unsigned long long a, unsigned long long b){
    unsigned long long r; asm("sub.rn.f32x2 %0,%1,%2;" : "=l"(r) : "l"(a), "l"(b)); return r;
}

// ---------------- FPS: one block per batch, 2 barriers/iteration ----------------
// Exact-rounding sub/mul/add distance chain (bit-identical trajectory).
// Reduction: warp redux -> swm[wid]; bar; EVERY warp redundantly reduces
// swm[lane] (no dedicated-warp phase); matchers atomicMin into double-buffered
// swin; bar; all threads read winner coords from the smem point mirror.
extern __shared__ float4 spts[];

__global__ __launch_bounds__(1024, 1) void fps_kernel(const float* __restrict__ xyz,
                                                      float* __restrict__ outxyz,
                                                      float* __restrict__ nxyz)
{
    int b = blockIdx.x, tid = threadIdx.x;
    int lane = tid & 31, wid = tid >> 5;
    const float* X = xyz + (size_t)b * 3 * NPTS;

    __shared__ unsigned swm[32];
    __shared__ int swin[2];

    unsigned long long x2[4], y2[4], z2[4];
    unsigned dist[8];
#pragma unroll
    for (int p = 0; p < 4; ++p) {
        int na = tid + (2*p)   * 1024;
        int nb = tid + (2*p+1) * 1024;
        float xa = X[na],        xbv = X[nb];
        float ya = X[NPTS+na],   yb  = X[NPTS+nb];
        float za = X[2*NPTS+na], zb  = X[2*NPTS+nb];
        x2[p] = pk2(xa, xbv); y2[p] = pk2(ya, yb); z2[p] = pk2(za, zb);
        spts[na] = make_float4(xa, ya, za, 0.f);
        spts[nb] = make_float4(xbv, yb, zb, 0.f);
        dist[2*p] = __float_as_uint(1e10f); dist[2*p+1] = __float_as_uint(1e10f);
    }
    if (tid < 2) swin[tid] = 0x7fffffff;
    __syncthreads();

    float4 c0 = spts[0];
    float cx = c0.x, cy = c0.y, cz = c0.z;

    for (int it = 0; it < NS; ++it) {
        if (tid == 0) {
            outxyz[(b*3 + 0)*NS + it] = cx;
            outxyz[(b*3 + 1)*NS + it] = cy;
            outxyz[(b*3 + 2)*NS + it] = cz;
            nxyz[((size_t)b*NS + it)*3 + 0] = cx;
            nxyz[((size_t)b*NS + it)*3 + 1] = cy;
            nxyz[((size_t)b*NS + it)*3 + 2] = cz;
        }
        unsigned long long cx2 = pk2(cx, cx);
        unsigned long long cy2 = pk2(cy, cy);
        unsigned long long cz2 = pk2(cz, cz);

#pragma unroll
        for (int p = 0; p < 4; ++p) {
            unsigned long long dx = f2sub(x2[p], cx2);
            unsigned long long dy = f2sub(y2[p], cy2);
            unsigned long long dz = f2sub(z2[p], cz2);
            unsigned long long s = f2add(f2add(f2mul(dx, dx), f2mul(dy, dy)), f2mul(dz, dz));
            unsigned slo, shi; upk2u(s, slo, shi);
            dist[2*p]   = min(dist[2*p],   slo);
            dist[2*p+1] = min(dist[2*p+1], shi);
        }
        unsigned m01 = max(dist[0], dist[1]), m23 = max(dist[2], dist[3]);
        unsigned m45 = max(dist[4], dist[5]), m67 = max(dist[6], dist[7]);
        unsigned key = max(max(m01, m23), max(m45, m67));

        unsigned kmax = __reduce_max_sync(0xffffffffu, key);
        if (lane == 0) swm[wid] = kmax;
        __syncthreads();                               // b1: swm complete
        unsigned g = __reduce_max_sync(0xffffffffu, swm[lane]);  // all warps
        if (tid == 0) swin[(it + 1) & 1] = 0x7fffffff; // reset next slot
        if (key == g) {                                // rare: 1-2 threads
            int li = 0x7fffffff;
#pragma unroll
            for (int p = 3; p >= 0; --p) {             // lo overwrites hi -> first occurrence
                if (dist[2*p+1] == g) li = tid + (2*p+1) * 1024;
                if (dist[2*p]   == g) li = tid + (2*p)   * 1024;
            }
            atomicMin(&swin[it & 1], li);              // min over threads -> global first
        }
        __syncthreads();                               // b2: winner ready
        float4 cc = spts[swin[it & 1]];
        cx = cc.x; cy = cc.y; cz = cc.z;
    }
}

// ---------------- ball query: one warp per center ----------------
__global__ __launch_bounds__(256) void ball_kernel(const float* __restrict__ xyz,
                                                   const float* __restrict__ nxyz,
                                                   int* __restrict__ gidx)
{
    __shared__ int sbuf[8][32];
    int w = threadIdx.x >> 5, lane = threadIdx.x & 31;
    int gid = blockIdx.x * 8 + w;
    int b = gid >> 11, s = gid & 2047;
    const float* X = xyz + (size_t)b * 3 * NPTS;

    float cx = nxyz[gid*3], cy = nxyz[gid*3 + 1], cz = nxyz[gid*3 + 2];
    float cc = __fadd_rn(__fadd_rn(__fmul_rn(cx,cx), __fmul_rn(cy,cy)), __fmul_rn(cz,cz));
    const float R2 = (float)(0.1 * 0.1);

    int cnt = 0;
    for (int base = 0; base < NPTS; base += 32) {
        int n = base + lane;
        float px = X[n], py = X[NPTS + n], pz = X[2*NPTS + n];
        float pp  = __fadd_rn(__fadd_rn(__fmul_rn(px,px), __fmul_rn(py,py)), __fmul_rn(pz,pz));
        float dot = __fadd_rn(__fadd_rn(__fmul_rn(cx,px), __fmul_rn(cy,py)), __fmul_rn(cz,pz));
        float sqr = __fadd_rn(__fadd_rn(cc, pp), -__fmul_rn(2.f, dot));
        bool hit = (sqr <= R2);
        unsigned m = __ballot_sync(0xffffffffu, hit);
        if (m) {
            int rank = cnt + __popc(m & ((1u << lane) - 1u));
            if (hit && rank < 32) sbuf[w][rank] = n;
            cnt += __popc(m);
            if (cnt >= 32) break;
        }
    }
    __syncwarp();
    int first = sbuf[w][0];
    int my = (lane < cnt) ? sbuf[w][lane] : first;
    gidx[((size_t)(b*32 + lane))*2048 + s] = my;
}

// ---------------- gather + center-subtract + concat ----------------
__global__ __launch_bounds__(256) void gather_kernel(const float* __restrict__ xyz,
                                                     const float* __restrict__ pts,
                                                     const int* __restrict__ gidx,
                                                     const float* __restrict__ nxyz,
                                                     float* __restrict__ xin)
{
    int g = blockIdx.x * 256 + threadIdx.x;
    int s = g & 2047, k = (g >> 11) & 31, b = g >> 16;
    int id = gidx[((size_t)(b*32 + k))*2048 + s];
    const float* X = xyz + (size_t)b * 3 * NPTS;
    const float* P = pts + (size_t)b * 29 * NPTS;
    size_t ob = (size_t)b * 32 * MPB + (size_t)k * 2048 + s;
#pragma unroll
    for (int c = 0; c < 3; ++c)
        xin[ob + (size_t)c * MPB] = X[c*NPTS + id] - nxyz[((size_t)(b*2048 + s))*3 + c];
#pragma unroll
    for (int c = 0; c < 29; ++c)
        xin[ob + (size_t)(3 + c) * MPB] = P[c*NPTS + id];
}

// ---------------- conv v2: smem-staged input, 256 thr, fused stats ----------------
template<int CIN, bool ACT>
__global__ __launch_bounds__(256) void conv_kernel(const float* __restrict__ in,
                                                   const float* __restrict__ W,
                                                   const float* __restrict__ aff,
                                                   float* __restrict__ out,
                                                   float* __restrict__ ps,
                                                   float* __restrict__ pq)
{
    constexpr int CH = CIN / 8;                // channel chunks of 8
    __shared__ float sW[CIN][64];
    __shared__ float sX[2][8][128];
    __shared__ float sA[64], sD[64];
    int tid = threadIdx.x, lane = tid & 31, w = tid >> 5;
    int b = blockIdx.x >> 9, mblk = blockIdx.x & 511;
    const float* ip = in + (size_t)b * CIN * MPB + mblk * 128 + lane * 4;

    for (int i = tid; i < CIN * 64; i += 256)
        sW[i >> 6][i & 63] = W[(i & 63) * CIN + (i >> 6)];
    if (ACT) for (int i = tid; i < CIN; i += 256) { sA[i] = aff[i]; sD[i] = aff[64 + i]; }

    float4 xr0 = *(const float4*)(ip + (size_t)w * MPB);
    float4 xr  = (CH > 1) ? *(const float4*)(ip + (size_t)(8 + w) * MPB) : xr0;
    __syncthreads();
    {
        float4 v = xr0;
        if (ACT) { float a = sA[w], d = sD[w];
            v.x = fmaxf(fmaf(a, v.x, d), 0.f); v.y = fmaxf(fmaf(a, v.y, d), 0.f);
            v.z = fmaxf(fmaf(a, v.z, d), 0.f); v.w = fmaxf(fmaf(a, v.w, d), 0.f); }
        *(float4*)&sX[0][w][lane * 4] = v;
    }
    __syncthreads();

    int og = w * 8;
    unsigned long long acc[4][4];
#pragma unroll
    for (int p = 0; p < 4; ++p)
#pragma unroll
        for (int j = 0; j < 4; ++j) acc[p][j] = 0ull;

    for (int k = 0; k < CH; ++k) {
#pragma unroll
        for (int cc = 0; cc < 8; ++cc) {
            int c = k * 8 + cc;
            float4 x = *(const float4*)&sX[k & 1][cc][lane * 4];
            unsigned long long xp[4] = { pk2(x.x, x.x), pk2(x.y, x.y),
                                         pk2(x.z, x.z), pk2(x.w, x.w) };
            const double2* wp = (const double2*)&sW[c][og];
            double2 w0 = wp[0], w1 = wp[1];
            unsigned long long wq[4] = {
                __double_as_longlong(w0.x), __double_as_longlong(w0.y),
                __double_as_longlong(w1.x), __double_as_longlong(w1.y) };
#pragma unroll
            for (int p = 0; p < 4; ++p)
#pragma unroll
                for (int j = 0; j < 4; ++j)
                    acc[p][j] = f2fma(wq[p], xp[j], acc[p][j]);
        }
        if (k + 1 < CH) {
            float4 v = xr;
            if (ACT) { int ch = (k + 1) * 8 + w; float a = sA[ch], d = sD[ch];
                v.x = fmaxf(fmaf(a, v.x, d), 0.f); v.y = fmaxf(fmaf(a, v.y, d), 0.f);
                v.z = fmaxf(fmaf(a, v.z, d), 0.f); v.w = fmaxf(fmaf(a, v.w, d), 0.f); }
            *(float4*)&sX[(k + 1) & 1][w][lane * 4] = v;
            if (k + 2 < CH) xr = *(const float4*)(ip + (size_t)((k + 2) * 8 + w) * MPB);
        }
        __syncthreads();
    }

    float* op = out + (size_t)b * 64 * MPB + mblk * 128 + lane * 4;
    int pblk = b * 512 + mblk;
#pragma unroll
    for (int p = 0; p < 4; ++p) {
        float4 vlo, vhi;
        upk2(acc[p][0], vlo.x, vhi.x); upk2(acc[p][1], vlo.y, vhi.y);
        upk2(acc[p][2], vlo.z, vhi.z); upk2(acc[p][3], vlo.w, vhi.w);
        *(float4*)(op + (size_t)(og + 2*p)     * MPB) = vlo;
        *(float4*)(op + (size_t)(og + 2*p + 1) * MPB) = vhi;
        float sl = vlo.x + vlo.y + vlo.z + vlo.w;
        float ql = vlo.x*vlo.x + vlo.y*vlo.y + vlo.z*vlo.z + vlo.w*vlo.w;
        float sh = vhi.x + vhi.y + vhi.z + vhi.w;
        float qh = vhi.x*vhi.x + vhi.y*vhi.y + vhi.z*vhi.z + vhi.w*vhi.w;
#pragma unroll
        for (int off = 16; off; off >>= 1) {
            sl += __shfl_xor_sync(0xffffffffu, sl, off);
            ql += __shfl_xor_sync(0xffffffffu, ql, off);
            sh += __shfl_xor_sync(0xffffffffu, sh, off);
            qh += __shfl_xor_sync(0xffffffffu, qh, off);
        }
        if (lane == 0) {
            ps[(og + 2*p)     * 2048 + pblk] = sl;
            pq[(og + 2*p)     * 2048 + pblk] = ql;
            ps[(og + 2*p + 1) * 2048 + pblk] = sh;
            pq[(og + 2*p + 1) * 2048 + pblk] = qh;
        }
    }
}

// ---------------- stage-2 stats: 2048 partials -> affine coeffs ----------------
__global__ __launch_bounds__(256) void statsfin2_kernel(const float* __restrict__ ps,
                                                        const float* __restrict__ pq,
                                                        const float* __restrict__ gam,
                                                        const float* __restrict__ bet,
                                                        float* __restrict__ aff)
{
    int o = blockIdx.x, tid = threadIdx.x;
    float s = 0.f, q = 0.f;
    for (int i = tid; i < 2048; i += 256) { s += ps[o*2048 + i]; q += pq[o*2048 + i]; }
    __shared__ float rs[256], rq[256];
    rs[tid] = s; rq[tid] = q;
    for (int off = 128; off; off >>= 1) {
        __syncthreads();
        if (tid < off) { rs[tid] += rs[tid + off]; rq[tid] += rq[tid + off]; }
    }
    if (tid == 0) {
        const float invn = 1.f / (float)(NB * MPB);
        float mean = rs[0] * invn;
        float var  = rq[0] * invn - mean * mean;
        float a = gam[o] * rsqrtf(var + 1e-5f);
        aff[o] = a;
        aff[64 + o] = bet[o] - a * mean;
    }
}

// ---------------- residual: x1 = relu(aff2(t2) + relu(aff0(y0))) ----------------
__global__ __launch_bounds__(256) void resid_kernel(const float* __restrict__ y0,
                                                    const float* __restrict__ t2,
                                                    const float* __restrict__ aff0,
                                                    const float* __restrict__ aff2,
                                                    float* __restrict__ x1)
{
    size_t i = (size_t)blockIdx.x * 256 + threadIdx.x;
    int c = (int)((i >> 14) & 63);
    float a0 = aff0[c], d0 = aff0[64+c], a2 = aff2[c], d2 = aff2[64+c];
    float4 y = ((const float4*)y0)[i];
    float4 t = ((const float4*)t2)[i];
    float4 r;
    r.x = fmaxf(fmaf(a2, t.x, d2) + fmaxf(fmaf(a0, y.x, d0), 0.f), 0.f);
    r.y = fmaxf(fmaf(a2, t.y, d2) + fmaxf(fmaf(a0, y.y, d0), 0.f), 0.f);
    r.z = fmaxf(fmaf(a2, t.z, d2) + fmaxf(fmaf(a0, y.z, d0), 0.f), 0.f);
    r.w = fmaxf(fmaf(a2, t.w, d2) + fmaxf(fmaf(a0, y.w, d0), 0.f), 0.f);
    ((float4*)x1)[i] = r;
}

// ---------------- final: feat = max_k relu(aff4(t4) + x1) ----------------
__global__ __launch_bounds__(256) void finalmax_kernel(const float* __restrict__ t4,
                                                       const float* __restrict__ x1,
                                                       const float* __restrict__ aff,
                                                       float* __restrict__ outf)
{
    int g = blockIdx.x * 256 + threadIdx.x;
    int s = g & 2047, o = (g >> 11) & 63, b = g >> 17;
    float a = aff[o], d = aff[64 + o];
    size_t base = (size_t)(b*64 + o) * MPB + s;
    const float* tp = t4 + base;
    const float* xp = x1 + base;
    float m = -1e30f;
#pragma unroll 8
    for (int k = 0; k < 32; ++k)
        m = fmaxf(m, fmaf(a, tp[(size_t)k*2048], d) + xp[(size_t)k*2048]);
    outf[g] = fmaxf(m, 0.f);
}

extern "C" void kernel_launch(void* const* d_in, const int* in_sizes, int n_in,
                              void* d_out, int out_size)
{
    (void)in_sizes; (void)n_in; (void)out_size;
    const float* xyz = (const float*)d_in[0];
    const float* pts = (const float*)d_in[1];
    const float* pw  = (const float*)d_in[2];
    const float* pg  = (const float*)d_in[3];
    const float* pb  = (const float*)d_in[4];
    const float* w1  = (const float*)d_in[5];
    const float* g1  = (const float*)d_in[6];
    const float* b1  = (const float*)d_in[7];
    const float* w2  = (const float*)d_in[8];
    const float* g2  = (const float*)d_in[9];
    const float* b2  = (const float*)d_in[10];

    float *y0, *t1, *t2, *x1, *nx, *ps, *pq, *aff; int* gi;
    cudaGetSymbolAddress((void**)&y0,  g_y0);
    cudaGetSymbolAddress((void**)&t1,  g_t1);
    cudaGetSymbolAddress((void**)&t2,  g_t2);
    cudaGetSymbolAddress((void**)&x1,  g_x1);
    cudaGetSymbolAddress((void**)&nx,  g_nxyz);
    cudaGetSymbolAddress((void**)&gi,  g_idx);
    cudaGetSymbolAddress((void**)&ps,  g_ps);
    cudaGetSymbolAddress((void**)&pq,  g_pq);
    cudaGetSymbolAddress((void**)&aff, g_aff);
    float* out = (float*)d_out;

    cudaFuncSetAttribute(fps_kernel, cudaFuncAttributeMaxDynamicSharedMemorySize,
                         NPTS * (int)sizeof(float4));

    fps_kernel<<<NB, 1024, NPTS * sizeof(float4)>>>(xyz, out, nx);
    ball_kernel<<<1024, 256>>>(xyz, nx, gi);
    gather_kernel<<<1024, 256>>>(xyz, pts, gi, nx, t2);

    conv_kernel<32, false><<<2048, 256>>>(t2, pw, nullptr, y0, ps, pq);
    statsfin2_kernel<<<64, 256>>>(ps, pq, pg, pb, aff);

    conv_kernel<64, true><<<2048, 256>>>(y0, w1, aff, t1, ps, pq);
    statsfin2_kernel<<<64, 256>>>(ps, pq, g1, b1, aff + 128);

    conv_kernel<64, true><<<2048, 256>>>(t1, w2, aff + 128, t2, ps, pq);
    statsfin2_kernel<<<64, 256>>>(ps, pq, g2, b2, aff + 256);

    resid_kernel<<<16384, 256>>>(y0, t2, aff, aff + 256, x1);

    conv_kernel<64, false><<<2048, 256>>>(x1, w1 + 4096, nullptr, t1, ps, pq);
    statsfin2_kernel<<<64, 256>>>(ps, pq, g1 + 64, b1 + 64, aff + 384);

    conv_kernel<64, true><<<2048, 256>>>(t1, w2 + 4096, aff + 384, t2, ps, pq);
    statsfin2_kernel<<<64, 256>>>(ps, pq, g2 + 64, b2 + 64, aff + 512);

    finalmax_kernel<<<2048, 256>>>(t2, x1, aff + 512, out + NB*3*NS);
}

// round 8
// speedup vs baseline: 1.4965x; 1.0610x over previous
#include <cuda_runtime.h>
#include <cstdint>

#define NPTS 8192
#define NS   2048
#define NK   32
#define NB   4
#define MPB  65536              /* NK*NS per batch */
#define FSZ  (NB*64*MPB)        /* 16.7M floats per feature buffer */
#define NPB  1024               /* stats partial blocks (4*256) */

__device__ float g_y0[FSZ];
__device__ float g_t1[FSZ];
__device__ float g_t2[FSZ];
__device__ float g_x1[FSZ];
__device__ float g_nxyz[NB*NS*3];
__device__ int   g_idx[NB*NK*NS];
__device__ float g_ps[64*2048];
__device__ float g_pq[64*2048];
__device__ float g_aff[5*128];

static __device__ __forceinline__ unsigned long long pk2(float lo, float hi){
    unsigned long long r; asm("mov.b64 %0,{%1,%2};" : "=l"(r) : "f"(lo), "f"(hi)); return r;
}
static __device__ __forceinline__ void upk2(unsigned long long v, float& lo, float& hi){
    asm("mov.b64 {%0,%1},%2;" : "=f"(lo), "=f"(hi) : "l"(v));
}
static __device__ __forceinline__ void upk2u(unsigned long long v, unsigned& lo, unsigned& hi){
    asm("mov.b64 {%0,%1},%2;" : "=r"(lo), "=r"(hi) : "l"(v));
}
static __device__ __forceinline__ unsigned long long f2fma(unsigned long long a, unsigned long long b, unsigned long long c){
    unsigned long long r; asm("fma.rn.f32x2 %0,%1,%2,%3;" : "=l"(r) : "l"(a), "l"(b), "l"(c)); return r;
}
static __device__ __forceinline__ unsigned long long f2mul(unsigned long long a, unsigned long long b){
    unsigned long long r; asm("mul.rn.f32x2 %0,%1,%2;" : "=l"(r) : "l"(a), "l"(b)); return r;
}
static __device__ __forceinline__ unsigned long long f2add(unsigned long long a, unsigned long long b){
    unsigned long long r; asm("add.rn.f32x2 %0,%1,%2;" : "=l"(r) : "l"(a), "l"(b)); return r;
}
static __device__ __forceinline__ unsigned long long f2sub(unsigned long long a, unsigned long long b){
    unsigned long long r; asm("sub.rn.f32x2 %0,%1,%2;" : "=l"(r) : "l"(a), "l"(b)); return r;
}

// ---------------- FPS: one block/batch, 512 threads x 16 points ----------------
// Exact-rounding sub/mul/add distance chain; min/max as uint (monotonic for
// nonneg floats); deferred first-occurrence argmax; 2 barriers/iteration.
extern __shared__ float4 spts[];

__global__ __launch_bounds__(512, 1) void fps_kernel(const float* __restrict__ xyz,
                                                     float* __restrict__ outxyz,
                                                     float* __restrict__ nxyz)
{
    int b = blockIdx.x, tid = threadIdx.x;
    int lane = tid & 31, wid = tid >> 5;     // 16 warps
    const float* X = xyz + (size_t)b * 3 * NPTS;

    __shared__ unsigned swm[32];
    __shared__ int swin[2];

    unsigned long long x2[8], y2[8], z2[8];
    unsigned dist[16];
#pragma unroll
    for (int p = 0; p < 8; ++p) {
        int na = tid + (2*p)   * 512;
        int nb = tid + (2*p+1) * 512;
        float xa = X[na],        xbv = X[nb];
        float ya = X[NPTS+na],   yb  = X[NPTS+nb];
        float za = X[2*NPTS+na], zb  = X[2*NPTS+nb];
        x2[p] = pk2(xa, xbv); y2[p] = pk2(ya, yb); z2[p] = pk2(za, zb);
        spts[na] = make_float4(xa, ya, za, 0.f);
        spts[nb] = make_float4(xbv, yb, zb, 0.f);
        dist[2*p] = __float_as_uint(1e10f); dist[2*p+1] = __float_as_uint(1e10f);
    }
    if (tid < 2) swin[tid] = 0x7fffffff;
    if (tid >= 16 && tid < 32) swm[tid] = 0u;   // pad for full-warp redux
    __syncthreads();

    float4 c0 = spts[0];
    float cx = c0.x, cy = c0.y, cz = c0.z;

    for (int it = 0; it < NS; ++it) {
        if (tid == 0) {
            outxyz[(b*3 + 0)*NS + it] = cx;
            outxyz[(b*3 + 1)*NS + it] = cy;
            outxyz[(b*3 + 2)*NS + it] = cz;
            nxyz[((size_t)b*NS + it)*3 + 0] = cx;
            nxyz[((size_t)b*NS + it)*3 + 1] = cy;
            nxyz[((size_t)b*NS + it)*3 + 2] = cz;
        }
        unsigned long long cx2 = pk2(cx, cx);
        unsigned long long cy2 = pk2(cy, cy);
        unsigned long long cz2 = pk2(cz, cz);

#pragma unroll
        for (int p = 0; p < 8; ++p) {
            unsigned long long dx = f2sub(x2[p], cx2);
            unsigned long long dy = f2sub(y2[p], cy2);
            unsigned long long dz = f2sub(z2[p], cz2);
            unsigned long long s = f2add(f2add(f2mul(dx, dx), f2mul(dy, dy)), f2mul(dz, dz));
            unsigned slo, shi; upk2u(s, slo, shi);
            dist[2*p]   = min(dist[2*p],   slo);
            dist[2*p+1] = min(dist[2*p+1], shi);
        }
        unsigned key = 0u;
#pragma unroll
        for (int j = 0; j < 16; ++j) key = max(key, dist[j]);

        unsigned kmax = __reduce_max_sync(0xffffffffu, key);
        if (lane == 0) swm[wid] = kmax;
        __syncthreads();                               // b1: swm complete
        unsigned g = __reduce_max_sync(0xffffffffu, swm[lane]);  // every warp
        if (tid == 0) swin[(it + 1) & 1] = 0x7fffffff;
        if (key == g) {                                // rare: 1-2 threads
            int li = 0x7fffffff;
#pragma unroll
            for (int p = 7; p >= 0; --p) {             // lo overwrites hi -> first occurrence
                if (dist[2*p+1] == g) li = tid + (2*p+1) * 512;
                if (dist[2*p]   == g) li = tid + (2*p)   * 512;
            }
            atomicMin(&swin[it & 1], li);
        }
        __syncthreads();                               // b2: winner ready
        float4 cc = spts[swin[it & 1]];
        cx = cc.x; cy = cc.y; cz = cc.z;
    }
}

// ---------------- ball query: one warp per center ----------------
__global__ __launch_bounds__(256) void ball_kernel(const float* __restrict__ xyz,
                                                   const float* __restrict__ nxyz,
                                                   int* __restrict__ gidx)
{
    __shared__ int sbuf[8][32];
    int w = threadIdx.x >> 5, lane = threadIdx.x & 31;
    int gid = blockIdx.x * 8 + w;
    int b = gid >> 11, s = gid & 2047;
    const float* X = xyz + (size_t)b * 3 * NPTS;

    float cx = nxyz[gid*3], cy = nxyz[gid*3 + 1], cz = nxyz[gid*3 + 2];
    float cc = __fadd_rn(__fadd_rn(__fmul_rn(cx,cx), __fmul_rn(cy,cy)), __fmul_rn(cz,cz));
    const float R2 = (float)(0.1 * 0.1);

    int cnt = 0;
    for (int base = 0; base < NPTS; base += 32) {
        int n = base + lane;
        float px = X[n], py = X[NPTS + n], pz = X[2*NPTS + n];
        float pp  = __fadd_rn(__fadd_rn(__fmul_rn(px,px), __fmul_rn(py,py)), __fmul_rn(pz,pz));
        float dot = __fadd_rn(__fadd_rn(__fmul_rn(cx,px), __fmul_rn(cy,py)), __fmul_rn(cz,pz));
        float sqr = __fadd_rn(__fadd_rn(cc, pp), -__fmul_rn(2.f, dot));
        bool hit = (sqr <= R2);
        unsigned m = __ballot_sync(0xffffffffu, hit);
        if (m) {
            int rank = cnt + __popc(m & ((1u << lane) - 1u));
            if (hit && rank < 32) sbuf[w][rank] = n;
            cnt += __popc(m);
            if (cnt >= 32) break;
        }
    }
    __syncwarp();
    int first = sbuf[w][0];
    int my = (lane < cnt) ? sbuf[w][lane] : first;
    gidx[((size_t)(b*32 + lane))*2048 + s] = my;
}

// ---------------- gather + center-subtract + concat ----------------
__global__ __launch_bounds__(256) void gather_kernel(const float* __restrict__ xyz,
                                                     const float* __restrict__ pts,
                                                     const int* __restrict__ gidx,
                                                     const float* __restrict__ nxyz,
                                                     float* __restrict__ xin)
{
    int g = blockIdx.x * 256 + threadIdx.x;
    int s = g & 2047, k = (g >> 11) & 31, b = g >> 16;
    int id = gidx[((size_t)(b*32 + k))*2048 + s];
    const float* X = xyz + (size_t)b * 3 * NPTS;
    const float* P = pts + (size_t)b * 29 * NPTS;
    size_t ob = (size_t)b * 32 * MPB + (size_t)k * 2048 + s;
#pragma unroll
    for (int c = 0; c < 3; ++c)
        xin[ob + (size_t)c * MPB] = X[c*NPTS + id] - nxyz[((size_t)(b*2048 + s))*3 + c];
#pragma unroll
    for (int c = 0; c < 29; ++c)
        xin[ob + (size_t)(3 + c) * MPB] = P[c*NPTS + id];
}

// ---------------- conv v3: 256 pts/block, 8 pts/thread, fused stats ----------------
// Thread (w=warp, lane): outputs og..og+7 (og=w*8), points {4l..4l+3} and
// {128+4l..128+4l+3} of the block's 256. acc[p][j]: output pair (og+2p,og+2p+1),
// point j (j<4: first group, j>=4: second). Channel accumulation order ascending
// -> conv results bit-identical to prior rounds.
template<int CIN, bool ACT>
__global__ __launch_bounds__(256) void conv_kernel(const float* __restrict__ in,
                                                   const float* __restrict__ W,
                                                   const float* __restrict__ aff,
                                                   float* __restrict__ out,
                                                   float* __restrict__ ps,
                                                   float* __restrict__ pq)
{
    constexpr int CH = CIN / 8;
    __shared__ float sW[CIN][64];
    __shared__ float sX[2][8][256];
    __shared__ float sA[64], sD[64];
    int tid = threadIdx.x, lane = tid & 31, w = tid >> 5;
    int b = blockIdx.x >> 8, mblk = blockIdx.x & 255;
    const float* ip = in + (size_t)b * CIN * MPB + mblk * 256;

    for (int i = tid; i < CIN * 64; i += 256)
        sW[i >> 6][i & 63] = W[(i & 63) * CIN + (i >> 6)];
    if (ACT) for (int i = tid; i < CIN; i += 256) { sA[i] = aff[i]; sD[i] = aff[64 + i]; }

    float4 xa = *(const float4*)(ip + (size_t)w * MPB + lane * 4);
    float4 xb = *(const float4*)(ip + (size_t)w * MPB + 128 + lane * 4);
    float4 na, nb;
    if (CH > 1) {
        na = *(const float4*)(ip + (size_t)(8 + w) * MPB + lane * 4);
        nb = *(const float4*)(ip + (size_t)(8 + w) * MPB + 128 + lane * 4);
    }
    __syncthreads();                            // sW/sA visible
    {
        float4 va = xa, vb = xb;
        if (ACT) { float a = sA[w], d = sD[w];
            va.x = fmaxf(fmaf(a, va.x, d), 0.f); va.y = fmaxf(fmaf(a, va.y, d), 0.f);
            va.z = fmaxf(fmaf(a, va.z, d), 0.f); va.w = fmaxf(fmaf(a, va.w, d), 0.f);
            vb.x = fmaxf(fmaf(a, vb.x, d), 0.f); vb.y = fmaxf(fmaf(a, vb.y, d), 0.f);
            vb.z = fmaxf(fmaf(a, vb.z, d), 0.f); vb.w = fmaxf(fmaf(a, vb.w, d), 0.f); }
        *(float4*)&sX[0][w][lane * 4]       = va;
        *(float4*)&sX[0][w][128 + lane * 4] = vb;
    }
    __syncthreads();                            // sX[0] ready

    int og = w * 8;
    unsigned long long acc[4][8];
#pragma unroll
    for (int p = 0; p < 4; ++p)
#pragma unroll
        for (int j = 0; j < 8; ++j) acc[p][j] = 0ull;

    for (int k = 0; k < CH; ++k) {
#pragma unroll
        for (int cc = 0; cc < 8; ++cc) {
            int c = k * 8 + cc;
            float4 ua = *(const float4*)&sX[k & 1][cc][lane * 4];
            float4 ub = *(const float4*)&sX[k & 1][cc][128 + lane * 4];
            unsigned long long xp[8] = { pk2(ua.x, ua.x), pk2(ua.y, ua.y),
                                         pk2(ua.z, ua.z), pk2(ua.w, ua.w),
                                         pk2(ub.x, ub.x), pk2(ub.y, ub.y),
                                         pk2(ub.z, ub.z), pk2(ub.w, ub.w) };
            const double2* wp = (const double2*)&sW[c][og];
            double2 w0 = wp[0], w1 = wp[1];
            unsigned long long wq[4] = {
                __double_as_longlong(w0.x), __double_as_longlong(w0.y),
                __double_as_longlong(w1.x), __double_as_longlong(w1.y) };
#pragma unroll
            for (int p = 0; p < 4; ++p)
#pragma unroll
                for (int j = 0; j < 8; ++j)
                    acc[p][j] = f2fma(wq[p], xp[j], acc[p][j]);
        }
        if (k + 1 < CH) {
            float4 va = na, vb = nb;
            if (ACT) { int ch = (k + 1) * 8 + w; float a = sA[ch], d = sD[ch];
                va.x = fmaxf(fmaf(a, va.x, d), 0.f); va.y = fmaxf(fmaf(a, va.y, d), 0.f);
                va.z = fmaxf(fmaf(a, va.z, d), 0.f); va.w = fmaxf(fmaf(a, va.w, d), 0.f);
                vb.x = fmaxf(fmaf(a, vb.x, d), 0.f); vb.y = fmaxf(fmaf(a, vb.y, d), 0.f);
                vb.z = fmaxf(fmaf(a, vb.z, d), 0.f); vb.w = fmaxf(fmaf(a, vb.w, d), 0.f); }
            *(float4*)&sX[(k + 1) & 1][w][lane * 4]       = va;
            *(float4*)&sX[(k + 1) & 1][w][128 + lane * 4] = vb;
            if (k + 2 < CH) {
                na = *(const float4*)(ip + (size_t)((k + 2) * 8 + w) * MPB + lane * 4);
                nb = *(const float4*)(ip + (size_t)((k + 2) * 8 + w) * MPB + 128 + lane * 4);
            }
        }
        __syncthreads();
    }

    float* op = out + (size_t)b * 64 * MPB + mblk * 256;
    int pblk = b * 256 + mblk;
#pragma unroll
    for (int p = 0; p < 4; ++p) {
        float4 a0, a1, b0, b1;
        upk2(acc[p][0], a0.x, a1.x); upk2(acc[p][1], a0.y, a1.y);
        upk2(acc[p][2], a0.z, a1.z); upk2(acc[p][3], a0.w, a1.w);
        upk2(acc[p][4], b0.x, b1.x); upk2(acc[p][5], b0.y, b1.y);
        upk2(acc[p][6], b0.z, b1.z); upk2(acc[p][7], b0.w, b1.w);
        int o0 = og + 2*p, o1 = og + 2*p + 1;
        *(float4*)(op + (size_t)o0 * MPB + lane * 4)       = a0;
        *(float4*)(op + (size_t)o0 * MPB + 128 + lane * 4) = b0;
        *(float4*)(op + (size_t)o1 * MPB + lane * 4)       = a1;
        *(float4*)(op + (size_t)o1 * MPB + 128 + lane * 4) = b1;
        float s0 = (a0.x + a0.y + a0.z + a0.w) + (b0.x + b0.y + b0.z + b0.w);
        float q0 = (a0.x*a0.x + a0.y*a0.y + a0.z*a0.z + a0.w*a0.w)
                 + (b0.x*b0.x + b0.y*b0.y + b0.z*b0.z + b0.w*b0.w);
        float s1 = (a1.x + a1.y + a1.z + a1.w) + (b1.x + b1.y + b1.z + b1.w);
        float q1 = (a1.x*a1.x + a1.y*a1.y + a1.z*a1.z + a1.w*a1.w)
                 + (b1.x*b1.x + b1.y*b1.y + b1.z*b1.z + b1.w*b1.w);
#pragma unroll
        for (int off = 16; off; off >>= 1) {
            s0 += __shfl_xor_sync(0xffffffffu, s0, off);
            q0 += __shfl_xor_sync(0xffffffffu, q0, off);
            s1 += __shfl_xor_sync(0xffffffffu, s1, off);
            q1 += __shfl_xor_sync(0xffffffffu, q1, off);
        }
        if (lane == 0) {
            ps[o0 * NPB + pblk] = s0;  pq[o0 * NPB + pblk] = q0;
            ps[o1 * NPB + pblk] = s1;  pq[o1 * NPB + pblk] = q1;
        }
    }
}

// ---------------- stage-2 stats: NPB partials -> affine coeffs ----------------
__global__ __launch_bounds__(256) void statsfin2_kernel(const float* __restrict__ ps,
                                                        const float* __restrict__ pq,
                                                        const float* __restrict__ gam,
                                                        const float* __restrict__ bet,
                                                        float* __restrict__ aff)
{
    int o = blockIdx.x, tid = threadIdx.x;
    float s = 0.f, q = 0.f;
    for (int i = tid; i < NPB; i += 256) { s += ps[o*NPB + i]; q += pq[o*NPB + i]; }
    __shared__ float rs[256], rq[256];
    rs[tid] = s; rq[tid] = q;
    for (int off = 128; off; off >>= 1) {
        __syncthreads();
        if (tid < off) { rs[tid] += rs[tid + off]; rq[tid] += rq[tid + off]; }
    }
    if (tid == 0) {
        const float invn = 1.f / (float)(NB * MPB);
        float mean = rs[0] * invn;
        float var  = rq[0] * invn - mean * mean;
        float a = gam[o] * rsqrtf(var + 1e-5f);
        aff[o] = a;
        aff[64 + o] = bet[o] - a * mean;
    }
}

// ---------------- residual: x1 = relu(aff2(t2) + relu(aff0(y0))) ----------------
__global__ __launch_bounds__(256) void resid_kernel(const float* __restrict__ y0,
                                                    const float* __restrict__ t2,
                                                    const float* __restrict__ aff0,
                                                    const float* __restrict__ aff2,
                                                    float* __restrict__ x1)
{
    size_t i = (size_t)blockIdx.x * 256 + threadIdx.x;
    int c = (int)((i >> 14) & 63);
    float a0 = aff0[c], d0 = aff0[64+c], a2 = aff2[c], d2 = aff2[64+c];
    float4 y = ((const float4*)y0)[i];
    float4 t = ((const float4*)t2)[i];
    float4 r;
    r.x = fmaxf(fmaf(a2, t.x, d2) + fmaxf(fmaf(a0, y.x, d0), 0.f), 0.f);
    r.y = fmaxf(fmaf(a2, t.y, d2) + fmaxf(fmaf(a0, y.y, d0), 0.f), 0.f);
    r.z = fmaxf(fmaf(a2, t.z, d2) + fmaxf(fmaf(a0, y.z, d0), 0.f), 0.f);
    r.w = fmaxf(fmaf(a2, t.w, d2) + fmaxf(fmaf(a0, y.w, d0), 0.f), 0.f);
    ((float4*)x1)[i] = r;
}

// ---------------- final: feat = max_k relu(aff4(t4) + x1) ----------------
__global__ __launch_bounds__(256) void finalmax_kernel(const float* __restrict__ t4,
                                                       const float* __restrict__ x1,
                                                       const float* __restrict__ aff,
                                                       float* __restrict__ outf)
{
    int g = blockIdx.x * 256 + threadIdx.x;
    int s = g & 2047, o = (g >> 11) & 63, b = g >> 17;
    float a = aff[o], d = aff[64 + o];
    size_t base = (size_t)(b*64 + o) * MPB + s;
    const float* tp = t4 + base;
    const float* xp = x1 + base;
    float m = -1e30f;
#pragma unroll 8
    for (int k = 0; k < 32; ++k)
        m = fmaxf(m, fmaf(a, tp[(size_t)k*2048], d) + xp[(size_t)k*2048]);
    outf[g] = fmaxf(m, 0.f);
}

extern "C" void kernel_launch(void* const* d_in, const int* in_sizes, int n_in,
                              void* d_out, int out_size)
{
    (void)in_sizes; (void)n_in; (void)out_size;
    const float* xyz = (const float*)d_in[0];
    const float* pts = (const float*)d_in[1];
    const float* pw  = (const float*)d_in[2];
    const float* pg  = (const float*)d_in[3];
    const float* pb  = (const float*)d_in[4];
    const float* w1  = (const float*)d_in[5];
    const float* g1  = (const float*)d_in[6];
    const float* b1  = (const float*)d_in[7];
    const float* w2  = (const float*)d_in[8];
    const float* g2  = (const float*)d_in[9];
    const float* b2  = (const float*)d_in[10];

    float *y0, *t1, *t2, *x1, *nx, *ps, *pq, *aff; int* gi;
    cudaGetSymbolAddress((void**)&y0,  g_y0);
    cudaGetSymbolAddress((void**)&t1,  g_t1);
    cudaGetSymbolAddress((void**)&t2,  g_t2);
    cudaGetSymbolAddress((void**)&x1,  g_x1);
    cudaGetSymbolAddress((void**)&nx,  g_nxyz);
    cudaGetSymbolAddress((void**)&gi,  g_idx);
    cudaGetSymbolAddress((void**)&ps,  g_ps);
    cudaGetSymbolAddress((void**)&pq,  g_pq);
    cudaGetSymbolAddress((void**)&aff, g_aff);
    float* out = (float*)d_out;

    cudaFuncSetAttribute(fps_kernel, cudaFuncAttributeMaxDynamicSharedMemorySize,
                         NPTS * (int)sizeof(float4));

    fps_kernel<<<NB, 512, NPTS * sizeof(float4)>>>(xyz, out, nx);
    ball_kernel<<<1024, 256>>>(xyz, nx, gi);
    gather_kernel<<<1024, 256>>>(xyz, pts, gi, nx, t2);

    conv_kernel<32, false><<<1024, 256>>>(t2, pw, nullptr, y0, ps, pq);
    statsfin2_kernel<<<64, 256>>>(ps, pq, pg, pb, aff);

    conv_kernel<64, true><<<1024, 256>>>(y0, w1, aff, t1, ps, pq);
    statsfin2_kernel<<<64, 256>>>(ps, pq, g1, b1, aff + 128);

    conv_kernel<64, true><<<1024, 256>>>(t1, w2, aff + 128, t2, ps, pq);
    statsfin2_kernel<<<64, 256>>>(ps, pq, g2, b2, aff + 256);

    resid_kernel<<<16384, 256>>>(y0, t2, aff, aff + 256, x1);

    conv_kernel<64, false><<<1024, 256>>>(x1, w1 + 4096, nullptr, t1, ps, pq);
    statsfin2_kernel<<<64, 256>>>(ps, pq, g1 + 64, b1 + 64, aff + 384);

    conv_kernel<64, true><<<1024, 256>>>(t1, w2 + 4096, aff + 384, t2, ps, pq);
    statsfin2_kernel<<<64, 256>>>(ps, pq, g2 + 64, b2 + 64, aff + 512);

    finalmax_kernel<<<2048, 256>>>(t2, x1, aff + 512, out + NB*3*NS);
}